// round 13
// baseline (speedup 1.0000x reference)
#include <cuda_runtime.h>
#include <cuda_bf16.h>

// Problem constants
#define Bn 8
#define Tn 1024
#define Fn 512
#define Dn 64
#define ROWS (Bn*Tn)       // 8192
#define TC 16              // scan chunk length
#define NCH 64             // scan chunks (Tn/TC)

// GEMM tiling
#define MBLK 64            // rows per block
#define NTOT 192           // total W rows (K|Q|V)
#define NKC2 8             // K chunks of 64
#define LDB2 144           // smem row stride bytes (64 bf16 = 128B + 16 pad)
#define OUTS 68            // Q epilogue fp32 tile stride
#define OUTS2 132          // KV epilogue fp32 tile stride (128 + 4)

// Q-GEMM smem (N=64): 2 stages of {A_hi,A_lo,B_hi,B_lo} 64 rows x 144B
#define SA_HI 0
#define SA_LO 9216
#define SB_HI 18432
#define SB_LO 27648
#define STGB  36864
#define SM_TOT (2*STGB)    // 73728

// KV-GEMM smem (N=128): 2 stages of {A_hi,A_lo (64r), B_hi,B_lo (128r)}
#define FA_HI 0
#define FA_LO 9216
#define FB_HI 18432
#define FB_LO 36864
#define FSTGB 55296
#define FSM_TOT (2*FSTGB)  // 110592

// Scan smem layout (floats)
#define SC_KC   0                      // [16][32]
#define SC_QC   (SC_KC + TC*32)        // [16][64]
#define SC_VC   (SC_QC + TC*Dn)        // [16][64]
#define SC_YP   (SC_VC + TC*Dn)        // float4[8][8][8] = 2048 floats
#define SC_TOTF (SC_YP + 8*8*8*4)      // 4608 floats = 18432 B

// Scratch
__device__ float g_K[ROWS*Dn];
__device__ float g_Q[ROWS*Dn];
__device__ float g_V[ROWS*Dn];
__device__ float g_S[Bn*NCH*Dn*Dn];        // 8MB chunk sums
__device__ float g_P[Bn*NCH*Dn*Dn];        // 8MB chunk-prefix states
__device__ unsigned short g_Whi[NTOT*Fn];
__device__ unsigned short g_Wlo[NTOT*Fn];
__device__ unsigned short g_Xhi[ROWS*Fn];
__device__ unsigned short g_Xlo[ROWS*Fn];

__device__ __forceinline__ unsigned smem_u32(const void* p){
    unsigned a;
    asm("{ .reg .u64 t; cvta.to.shared.u64 t, %1; cvt.u32.u64 %0, t; }" : "=r"(a) : "l"(p));
    return a;
}
__device__ __forceinline__ void cp16(unsigned dst, const void* src){
    asm volatile("cp.async.cg.shared.global [%0], [%1], 16;" :: "r"(dst), "l"(src));
}
#define CP_COMMIT() asm volatile("cp.async.commit_group;" ::: "memory")
#define CP_WAIT(n)  asm volatile("cp.async.wait_group %0;" :: "n"(n) : "memory")

#define LDSM4(r, addr) \
    asm volatile("ldmatrix.sync.aligned.m8n8.x4.shared.b16 {%0,%1,%2,%3}, [%4];" \
        : "=r"((r)[0]), "=r"((r)[1]), "=r"((r)[2]), "=r"((r)[3]) : "r"(addr))

#define MMA_BF16(d, a, b0, b1) \
    asm volatile("mma.sync.aligned.m16n8k16.row.col.f32.bf16.bf16.f32 " \
        "{%0,%1,%2,%3}, {%4,%5,%6,%7}, {%8,%9}, {%0,%1,%2,%3};" \
        : "+f"((d)[0]), "+f"((d)[1]), "+f"((d)[2]), "+f"((d)[3]) \
        : "r"((a)[0]), "r"((a)[1]), "r"((a)[2]), "r"((a)[3]), "r"(b0), "r"(b1))

__device__ __forceinline__ unsigned pack_bf2(float v0, float v1, unsigned short* lo0, unsigned short* lo1){
    __nv_bfloat16 h0 = __float2bfloat16(v0);
    __nv_bfloat16 h1 = __float2bfloat16(v1);
    *lo0 = __bfloat16_as_ushort(__float2bfloat16(v0 - __bfloat162float(h0)));
    *lo1 = __bfloat16_as_ushort(__float2bfloat16(v1 - __bfloat162float(h1)));
    return (unsigned)__bfloat16_as_ushort(h0) | ((unsigned)__bfloat16_as_ushort(h1) << 16);
}

// ---------------------------------------------------------------------------
// Fused prep: blocks [0,256) = LN+split x ; blocks [256,448) = W transpose+split
// ---------------------------------------------------------------------------
__global__ void __launch_bounds__(256) prep_kernel(
    const float* __restrict__ x,
    const float* __restrict__ Wk, const float* __restrict__ Wq,
    const float* __restrict__ Wv,
    const float* __restrict__ gamma, const float* __restrict__ beta)
{
    if (blockIdx.x >= 256) {
        const int n = blockIdx.x - 256;
        const int m = n >> 6, j = n & 63;
        const float* W = (m == 0) ? Wk : ((m == 1) ? Wq : Wv);
        const int k0 = threadIdx.x * 2;
        float v0 = __ldg(W + (size_t)k0*Dn + j);
        float v1 = __ldg(W + (size_t)(k0+1)*Dn + j);
        unsigned short l0, l1;
        unsigned hi = pack_bf2(v0, v1, &l0, &l1);
        unsigned lo = (unsigned)l0 | ((unsigned)l1 << 16);
        reinterpret_cast<unsigned*>(g_Whi)[n*(Fn/2) + threadIdx.x] = hi;
        reinterpret_cast<unsigned*>(g_Wlo)[n*(Fn/2) + threadIdx.x] = lo;
        return;
    }
    const int w = threadIdx.x >> 5, l = threadIdx.x & 31;
#pragma unroll 1
    for (int rr = 0; rr < 4; rr++) {
        const int row = blockIdx.x*32 + w*4 + rr;
        const float4* xr = reinterpret_cast<const float4*>(x + (size_t)row * Fn);
        float4 v[4];
        float s = 0.f, ss = 0.f;
#pragma unroll
        for (int q = 0; q < 4; q++) {
            v[q] = xr[q*32 + l];
            s  += v[q].x + v[q].y + v[q].z + v[q].w;
            ss += v[q].x*v[q].x + v[q].y*v[q].y + v[q].z*v[q].z + v[q].w*v[q].w;
        }
#pragma unroll
        for (int o = 16; o; o >>= 1) {
            s  += __shfl_xor_sync(0xffffffffu, s,  o);
            ss += __shfl_xor_sync(0xffffffffu, ss, o);
        }
        const float mu   = s * (1.f/512.f);
        const float var  = ss * (1.f/512.f) - mu*mu;
        const float rstd = rsqrtf(var + 1e-5f);
#pragma unroll
        for (int q = 0; q < 4; q++) {
            const int c4 = q*32 + l;
            float4 g4 = __ldg(reinterpret_cast<const float4*>(gamma) + c4);
            float4 b4 = __ldg(reinterpret_cast<const float4*>(beta)  + c4);
            float vv[4] = {v[q].x, v[q].y, v[q].z, v[q].w};
            float gg[4] = {g4.x, g4.y, g4.z, g4.w};
            float bb[4] = {b4.x, b4.y, b4.z, b4.w};
#pragma unroll
            for (int e = 0; e < 4; e++) vv[e] = (vv[e] - mu)*rstd*gg[e] + bb[e];
            unsigned short s0, s1, s2, s3;
            unsigned h0 = pack_bf2(vv[0], vv[1], &s0, &s1);
            unsigned h1 = pack_bf2(vv[2], vv[3], &s2, &s3);
            unsigned lo0 = (unsigned)s0 | ((unsigned)s1 << 16);
            unsigned lo1 = (unsigned)s2 | ((unsigned)s3 << 16);
            *reinterpret_cast<uint2*>(g_Xhi + (size_t)row*Fn + c4*4) = make_uint2(h0, h1);
            *reinterpret_cast<uint2*>(g_Xlo + (size_t)row*Fn + c4*4) = make_uint2(lo0, lo1);
        }
    }
}

// ---------------------------------------------------------------------------
// Fused KV-GEMM + chunk-sum. grid 128, 256 threads (8 warps: 2M x 4N(32)).
// ---------------------------------------------------------------------------
__global__ void __launch_bounds__(256) gemm_kv_kernel()
{
    extern __shared__ char smem[];
    const int tid = threadIdx.x, w = tid >> 5, l = tid & 31;
    const int mb = blockIdx.x;
    const int row0 = mb * MBLK;
    const unsigned sbase = smem_u32(smem);
    const int wm = w & 1, wn = w >> 1;

    const int sr = tid >> 2, seg = tid & 3;
    const char* srcAh = (const char*)(g_Xhi + (size_t)(row0 + sr)*Fn) + seg*32;
    const char* srcAl = (const char*)(g_Xlo + (size_t)(row0 + sr)*Fn) + seg*32;
    const char* srcB0h = (const char*)(g_Whi + (size_t)sr*Fn) + seg*32;          // K weights
    const char* srcB0l = (const char*)(g_Wlo + (size_t)sr*Fn) + seg*32;
    const char* srcB1h = (const char*)(g_Whi + (size_t)(128 + sr)*Fn) + seg*32;  // V weights
    const char* srcB1l = (const char*)(g_Wlo + (size_t)(128 + sr)*Fn) + seg*32;
    const unsigned dA  = sbase + (unsigned)sr*LDB2 + seg*32;
    const unsigned dB0 = sbase + (unsigned)sr*LDB2 + seg*32;
    const unsigned dB1 = sbase + (unsigned)(64 + sr)*LDB2 + seg*32;

    unsigned a_off[2], b_off[2];
#pragma unroll
    for (int mt = 0; mt < 2; mt++)
        a_off[mt] = sbase + FA_HI + (unsigned)(wm*32 + mt*16 + (l & 15))*LDB2 + ((l >> 4) << 4);
#pragma unroll
    for (int bb = 0; bb < 2; bb++)
        b_off[bb] = sbase + FB_HI
            + (unsigned)(wn*32 + bb*16 + ((l >> 4) << 3) + (l & 7))*LDB2 + (((l >> 3) & 1) << 4);

    float acc[2][4][4];
#pragma unroll
    for (int mt = 0; mt < 2; mt++)
#pragma unroll
        for (int nt = 0; nt < 4; nt++)
#pragma unroll
            for (int e = 0; e < 4; e++) acc[mt][nt][e] = 0.f;

    {
        cp16(dA + FA_HI, srcAh);   cp16(dA + FA_HI + 16, srcAh + 16);
        cp16(dA + FA_LO, srcAl);   cp16(dA + FA_LO + 16, srcAl + 16);
        cp16(dB0 + FB_HI, srcB0h); cp16(dB0 + FB_HI + 16, srcB0h + 16);
        cp16(dB0 + FB_LO, srcB0l); cp16(dB0 + FB_LO + 16, srcB0l + 16);
        cp16(dB1 + FB_HI, srcB1h); cp16(dB1 + FB_HI + 16, srcB1h + 16);
        cp16(dB1 + FB_LO, srcB1l); cp16(dB1 + FB_LO + 16, srcB1l + 16);
        CP_COMMIT();
    }

#pragma unroll 1
    for (int c = 0; c < NKC2; c++) {
        if (c < NKC2 - 1) {
            const unsigned st = ((c + 1) & 1)*FSTGB;
            const int o = (c + 1)*128;
            cp16(dA + st + FA_HI, srcAh + o);   cp16(dA + st + FA_HI + 16, srcAh + o + 16);
            cp16(dA + st + FA_LO, srcAl + o);   cp16(dA + st + FA_LO + 16, srcAl + o + 16);
            cp16(dB0 + st + FB_HI, srcB0h + o); cp16(dB0 + st + FB_HI + 16, srcB0h + o + 16);
            cp16(dB0 + st + FB_LO, srcB0l + o); cp16(dB0 + st + FB_LO + 16, srcB0l + o + 16);
            cp16(dB1 + st + FB_HI, srcB1h + o); cp16(dB1 + st + FB_HI + 16, srcB1h + o + 16);
            cp16(dB1 + st + FB_LO, srcB1l + o); cp16(dB1 + st + FB_LO + 16, srcB1l + o + 16);
            CP_COMMIT();
            CP_WAIT(1);
        } else {
            CP_WAIT(0);
        }
        __syncthreads();

        const unsigned so = (unsigned)(c & 1)*FSTGB;
#pragma unroll
        for (int ks = 0; ks < 4; ks++) {
            const unsigned koff = so + ks*32;
            unsigned ahi[2][4], alo[2][4], bhi[2][4], blo[2][4];
#pragma unroll
            for (int mt = 0; mt < 2; mt++) {
                LDSM4(ahi[mt], a_off[mt] + koff);
                LDSM4(alo[mt], a_off[mt] + koff + (FA_LO - FA_HI));
            }
#pragma unroll
            for (int bb = 0; bb < 2; bb++) {
                LDSM4(bhi[bb], b_off[bb] + koff);
                LDSM4(blo[bb], b_off[bb] + koff + (FB_LO - FB_HI));
            }
#pragma unroll
            for (int mt = 0; mt < 2; mt++)
#pragma unroll
                for (int nt = 0; nt < 4; nt++) {
                    const int p = nt >> 1, h = (nt & 1)*2;
                    MMA_BF16(acc[mt][nt], ahi[mt], bhi[p][h], bhi[p][h+1]);
                    MMA_BF16(acc[mt][nt], ahi[mt], blo[p][h], blo[p][h+1]);
                    MMA_BF16(acc[mt][nt], alo[mt], bhi[p][h], bhi[p][h+1]);
                }
        }
        __syncthreads();
    }

    float* outt = reinterpret_cast<float*>(smem);
#pragma unroll
    for (int mt = 0; mt < 2; mt++)
#pragma unroll
        for (int nt = 0; nt < 4; nt++) {
            const int r   = wm*32 + mt*16 + (l >> 2);
            const int col = wn*32 + nt*8 + (l & 3)*2;
            *reinterpret_cast<float2*>(&outt[r*OUTS2 + col])     = make_float2(acc[mt][nt][0], acc[mt][nt][1]);
            *reinterpret_cast<float2*>(&outt[(r+8)*OUTS2 + col]) = make_float2(acc[mt][nt][2], acc[mt][nt][3]);
        }
    __syncthreads();

#pragma unroll 1
    for (int r8 = 0; r8 < 8; r8++) {
        const int r = w*8 + r8;
        const int grow = row0 + r;
        float k0 = fmaxf(outt[r*OUTS2 + l], 0.f);
        float k1 = fmaxf(outt[r*OUTS2 + 32 + l], 0.f);
        float s = k0 + k1;
#pragma unroll
        for (int o = 16; o; o >>= 1) s += __shfl_xor_sync(0xffffffffu, s, o);
        const float rs = 1.f / (1e-5f + s);
        k0 *= rs; k1 *= rs;
        outt[r*OUTS2 + l]      = k0;
        outt[r*OUTS2 + 32 + l] = k1;
        g_K[(size_t)grow*Dn + l]      = k0;
        g_K[(size_t)grow*Dn + 32 + l] = k1;
        g_V[(size_t)grow*Dn + l]      = outt[r*OUTS2 + 64 + l];
        g_V[(size_t)grow*Dn + 32 + l] = outt[r*OUTS2 + 96 + l];
    }
    __syncthreads();

    const int jg = tid & 15, ig = tid >> 4;
#pragma unroll 1
    for (int ch = 0; ch < 4; ch++) {
        float a4[4][4] = {};
#pragma unroll
        for (int t = 0; t < TC; t++) {
            const int row = ch*16 + t;
            float4 k4 = *reinterpret_cast<const float4*>(&outt[row*OUTS2 + jg*4]);
            float4 v4 = *reinterpret_cast<const float4*>(&outt[row*OUTS2 + 64 + ig*4]);
            float kk[4] = {k4.x, k4.y, k4.z, k4.w};
            float vv[4] = {v4.x, v4.y, v4.z, v4.w};
#pragma unroll
            for (int i = 0; i < 4; i++)
#pragma unroll
                for (int j = 0; j < 4; j++) a4[i][j] += vv[i]*kk[j];
        }
        float* S = g_S + (size_t)(mb*4 + ch)*(Dn*Dn);
#pragma unroll
        for (int i = 0; i < 4; i++)
            *reinterpret_cast<float4*>(S + (ig*4 + i)*Dn + jg*4) =
                make_float4(a4[i][0], a4[i][1], a4[i][2], a4[i][3]);
    }
}

// ---------------------------------------------------------------------------
// Q-GEMM: grid 128, 256 threads (8 warps: 2M x 4N(16)), cp.async 2-stage.
// ---------------------------------------------------------------------------
__global__ void __launch_bounds__(256) gemm_q_kernel()
{
    extern __shared__ char smem[];
    const int tid = threadIdx.x, w = tid >> 5, l = tid & 31;
    const int mb = blockIdx.x;
    const int row0 = mb * MBLK;
    const unsigned sbase = smem_u32(smem);
    const int wm = w & 1, wn = w >> 1;

    const int sr = tid >> 2, seg = tid & 3;
    const char* srcAh = (const char*)(g_Xhi + (size_t)(row0 + sr)*Fn) + seg*32;
    const char* srcAl = (const char*)(g_Xlo + (size_t)(row0 + sr)*Fn) + seg*32;
    const char* srcBh = (const char*)(g_Whi + (size_t)(64 + sr)*Fn) + seg*32;
    const char* srcBl = (const char*)(g_Wlo + (size_t)(64 + sr)*Fn) + seg*32;
    const unsigned dbase = sbase + (unsigned)sr*LDB2 + seg*32;

    unsigned a_off[2];
#pragma unroll
    for (int mt = 0; mt < 2; mt++)
        a_off[mt] = sbase + SA_HI + (unsigned)(wm*32 + mt*16 + (l & 15))*LDB2 + ((l >> 4) << 4);
    const unsigned b_off = sbase + SB_HI
        + (unsigned)(wn*16 + ((l >> 4) << 3) + (l & 7))*LDB2 + (((l >> 3) & 1) << 4);

    float acc[2][2][4];
#pragma unroll
    for (int mt = 0; mt < 2; mt++)
#pragma unroll
        for (int nt = 0; nt < 2; nt++)
#pragma unroll
            for (int e = 0; e < 4; e++) acc[mt][nt][e] = 0.f;

    {
        const unsigned d = dbase;
        cp16(d + SA_HI, srcAh);  cp16(d + SA_HI + 16, srcAh + 16);
        cp16(d + SA_LO, srcAl);  cp16(d + SA_LO + 16, srcAl + 16);
        cp16(d + SB_HI, srcBh);  cp16(d + SB_HI + 16, srcBh + 16);
        cp16(d + SB_LO, srcBl);  cp16(d + SB_LO + 16, srcBl + 16);
        CP_COMMIT();
    }

#pragma unroll 1
    for (int c = 0; c < NKC2; c++) {
        if (c < NKC2 - 1) {
            const unsigned d = dbase + ((c + 1) & 1)*STGB;
            const int o = (c + 1)*128;
            cp16(d + SA_HI, srcAh + o);  cp16(d + SA_HI + 16, srcAh + o + 16);
            cp16(d + SA_LO, srcAl + o);  cp16(d + SA_LO + 16, srcAl + o + 16);
            cp16(d + SB_HI, srcBh + o);  cp16(d + SB_HI + 16, srcBh + o + 16);
            cp16(d + SB_LO, srcBl + o);  cp16(d + SB_LO + 16, srcBl + o + 16);
            CP_COMMIT();
            CP_WAIT(1);
        } else {
            CP_WAIT(0);
        }
        __syncthreads();

        const unsigned so = (unsigned)(c & 1)*STGB;
#pragma unroll
        for (int ks = 0; ks < 4; ks++) {
            const unsigned koff = so + ks*32;
            unsigned ahi[2][4], alo[2][4], bhi[4], blo[4];
#pragma unroll
            for (int mt = 0; mt < 2; mt++) {
                LDSM4(ahi[mt], a_off[mt] + koff);
                LDSM4(alo[mt], a_off[mt] + koff + (SA_LO - SA_HI));
            }
            LDSM4(bhi, b_off + koff);
            LDSM4(blo, b_off + koff + (SB_LO - SB_HI));
#pragma unroll
            for (int mt = 0; mt < 2; mt++)
#pragma unroll
                for (int nt = 0; nt < 2; nt++) {
                    const int h = nt*2;
                    MMA_BF16(acc[mt][nt], ahi[mt], bhi[h], bhi[h+1]);
                    MMA_BF16(acc[mt][nt], ahi[mt], blo[h], blo[h+1]);
                    MMA_BF16(acc[mt][nt], alo[mt], bhi[h], bhi[h+1]);
                }
        }
        __syncthreads();
    }

    float* outt = reinterpret_cast<float*>(smem);
#pragma unroll
    for (int mt = 0; mt < 2; mt++)
#pragma unroll
        for (int nt = 0; nt < 2; nt++) {
            const int r   = wm*32 + mt*16 + (l >> 2);
            const int col = wn*16 + nt*8 + (l & 3)*2;
            *reinterpret_cast<float2*>(&outt[r*OUTS + col])     = make_float2(acc[mt][nt][0], acc[mt][nt][1]);
            *reinterpret_cast<float2*>(&outt[(r+8)*OUTS + col]) = make_float2(acc[mt][nt][2], acc[mt][nt][3]);
        }
    __syncthreads();

#pragma unroll 1
    for (int r8 = 0; r8 < 8; r8++) {
        const int r = w*8 + r8;
        const int grow = row0 + r;
        float v0 = fmaxf(outt[r*OUTS + l], 0.f);
        float v1 = fmaxf(outt[r*OUTS + 32 + l], 0.f);
        float s = v0 + v1;
#pragma unroll
        for (int o = 16; o; o >>= 1) s += __shfl_xor_sync(0xffffffffu, s, o);
        const float rs = 1.f / (1e-5f + s);
        g_Q[(size_t)grow*Dn + l]      = v0 * rs;
        g_Q[(size_t)grow*Dn + 32 + l] = v1 * rs;
    }
}

// ---------------------------------------------------------------------------
// Prefix, fully parallel: one thread per (float4 element, chunk).
// grid (256, Bn) = 2048 blocks, 256 threads.
// Warp pair per element: warp h=0 covers chunks 0..31, h=1 covers 32..63.
// Inclusive shfl scan within warp; h=1 adds h=0's warp total via smem.
// ---------------------------------------------------------------------------
__global__ void __launch_bounds__(256) prefix_kernel(const float* __restrict__ state)
{
    __shared__ float4 tot[4];
    const int b = blockIdx.y;
    const int tid = threadIdx.x, w = tid >> 5, l = tid & 31;
    const int el = blockIdx.x*4 + (w >> 1);   // float4 element 0..1023
    const int h  = w & 1;
    const int c  = h*32 + l;                  // chunk 0..63
    const int e  = el*4;                      // float index

    float4 s4 = *reinterpret_cast<const float4*>(
        g_S + (size_t)(b*NCH + c)*(Dn*Dn) + e);

    // inclusive scan over lanes
    float4 inc = s4;
#pragma unroll
    for (int o = 1; o < 32; o <<= 1) {
        float ax = __shfl_up_sync(0xffffffffu, inc.x, o);
        float ay = __shfl_up_sync(0xffffffffu, inc.y, o);
        float az = __shfl_up_sync(0xffffffffu, inc.z, o);
        float aw = __shfl_up_sync(0xffffffffu, inc.w, o);
        if (l >= o) { inc.x += ax; inc.y += ay; inc.z += az; inc.w += aw; }
    }

    if (h == 0 && l == 31) tot[w >> 1] = inc;
    __syncthreads();

    float4 base = __ldg(reinterpret_cast<const float4*>(state + (size_t)b*(Dn*Dn) + e));
    if (h == 1) {
        float4 t = tot[w >> 1];
        base.x += t.x; base.y += t.y; base.z += t.z; base.w += t.w;
    }
    // exclusive = base + inc - s4
    float4 p;
    p.x = base.x + (inc.x - s4.x);
    p.y = base.y + (inc.y - s4.y);
    p.z = base.z + (inc.z - s4.z);
    p.w = base.w + (inc.w - s4.w);
    *reinterpret_cast<float4*>(g_P + (size_t)(b*NCH + c)*(Dn*Dn) + e) = p;
}

// ---------------------------------------------------------------------------
// Scan: grid (NCH, Bn, 2 j-halves) = 1024 blocks, 256 threads, TC=16.
// ---------------------------------------------------------------------------
__global__ void __launch_bounds__(256) scan_kernel(float* __restrict__ out)
{
    extern __shared__ float sm[];
    float*  Kc = sm + SC_KC;
    float*  Qc = sm + SC_QC;
    float*  Vc = sm + SC_VC;
    float4* ypbuf = reinterpret_cast<float4*>(sm + SC_YP);

    const int c = blockIdx.x, b = blockIdx.y, jh = blockIdx.z;
    const int tid = threadIdx.x, w = tid >> 5, l = tid & 31;
    const int ig = tid >> 3, jg = tid & 7;

    float acc[2][4];
    {
        const float* P = g_P + (size_t)(b*NCH + c)*(Dn*Dn) + jh*32 + jg*4;
#pragma unroll
        for (int i = 0; i < 2; i++) {
            float4 p = *reinterpret_cast<const float4*>(P + (ig*2 + i)*Dn);
            acc[i][0] = p.x; acc[i][1] = p.y; acc[i][2] = p.z; acc[i][3] = p.w;
        }
    }

    {
        const int base = (b*Tn + c*TC) * Dn;
        if (tid < 128) {
            const int t = tid >> 3, jj = (tid & 7)*4;
            *reinterpret_cast<float4*>(Kc + t*32 + jj) =
                *reinterpret_cast<const float4*>(g_K + base + t*Dn + jh*32 + jj);
        }
        {
            const int t = tid >> 4, jj = (tid & 15)*4;
            *reinterpret_cast<float4*>(Qc + t*Dn + jj) =
                *reinterpret_cast<const float4*>(g_Q + base + t*Dn + jj);
            *reinterpret_cast<float4*>(Vc + t*Dn + jj) =
                *reinterpret_cast<const float4*>(g_V + base + t*Dn + jj);
        }
    }
    __syncthreads();

    float* yout = out;
    float* sout = out + (size_t)ROWS * Dn;
    const int rbase0 = b*Tn + c*TC;

#pragma unroll 1
    for (int tg = 0; tg < TC/8; tg++) {
#pragma unroll
        for (int tt = 0; tt < 8; tt++) {
            const int t = tg*8 + tt;
            float4 k4 = *reinterpret_cast<const float4*>(Kc + t*32 + jg*4);
            float2 q2 = *reinterpret_cast<const float2*>(Qc + t*Dn + ig*2);
            float2 v2 = *reinterpret_cast<const float2*>(Vc + t*Dn + ig*2);
            const float kk[4] = {k4.x, k4.y, k4.z, k4.w};
            float yp[4] = {0.f, 0.f, 0.f, 0.f};
            float* srow = sout + (size_t)(rbase0 + t)*(Dn*Dn) + jh*32 + jg*4;

#pragma unroll
            for (int e = 0; e < 4; e++) { acc[0][e] += v2.x*kk[e]; yp[e] += acc[0][e]*q2.x; }
            __stcs(reinterpret_cast<float4*>(srow + (ig*2)*Dn),
                   make_float4(acc[0][0], acc[0][1], acc[0][2], acc[0][3]));
#pragma unroll
            for (int e = 0; e < 4; e++) { acc[1][e] += v2.y*kk[e]; yp[e] += acc[1][e]*q2.y; }
            __stcs(reinterpret_cast<float4*>(srow + (ig*2 + 1)*Dn),
                   make_float4(acc[1][0], acc[1][1], acc[1][2], acc[1][3]));

#pragma unroll
            for (int e = 0; e < 4; e++) {
                yp[e] += __shfl_xor_sync(0xffffffffu, yp[e], 8);
                yp[e] += __shfl_xor_sync(0xffffffffu, yp[e], 16);
            }
            if (l < 8) ypbuf[(tt*8 + w)*8 + l] = make_float4(yp[0], yp[1], yp[2], yp[3]);
        }
        __syncthreads();
        if (tid < 64) {
            const int tt = tid >> 3, jp = tid & 7;
            float4 s = make_float4(0.f, 0.f, 0.f, 0.f);
#pragma unroll
            for (int w8 = 0; w8 < 8; w8++) {
                float4 v = ypbuf[(tt*8 + w8)*8 + jp];
                s.x += v.x; s.y += v.y; s.z += v.z; s.w += v.w;
            }
            __stcs(reinterpret_cast<float4*>(
                yout + (size_t)(rbase0 + tg*8 + tt)*Dn + jh*32 + jp*4), s);
        }
        __syncthreads();
    }
}

// ---------------------------------------------------------------------------
extern "C" void kernel_launch(void* const* d_in, const int* in_sizes, int n_in,
                              void* d_out, int out_size)
{
    const float* x     = (const float*)d_in[0];
    const float* state = (const float*)d_in[1];
    const float* Wk    = (const float*)d_in[2];
    const float* Wq    = (const float*)d_in[3];
    const float* Wv    = (const float*)d_in[4];
    const float* gamma = (const float*)d_in[5];
    const float* beta  = (const float*)d_in[6];
    float* out = (float*)d_out;

    static cudaStream_t s1 = nullptr;
    static cudaEvent_t evA = nullptr, evB = nullptr;
    if (s1 == nullptr) {
        cudaStreamCreateWithFlags(&s1, cudaStreamNonBlocking);
        cudaEventCreateWithFlags(&evA, cudaEventDisableTiming);
        cudaEventCreateWithFlags(&evB, cudaEventDisableTiming);
        cudaFuncSetAttribute(gemm_kv_kernel, cudaFuncAttributeMaxDynamicSharedMemorySize, FSM_TOT);
        cudaFuncSetAttribute(gemm_q_kernel,  cudaFuncAttributeMaxDynamicSharedMemorySize, SM_TOT);
        cudaFuncSetAttribute(scan_kernel,    cudaFuncAttributeMaxDynamicSharedMemorySize, SC_TOTF*4);
    }

    prep_kernel<<<256 + NTOT, 256>>>(x, Wk, Wq, Wv, gamma, beta);
    cudaEventRecord(evA, 0);

    cudaStreamWaitEvent(s1, evA, 0);
    gemm_q_kernel<<<ROWS/MBLK, 256, SM_TOT, s1>>>();
    cudaEventRecord(evB, s1);

    gemm_kv_kernel<<<ROWS/MBLK, 256, FSM_TOT>>>();
    prefix_kernel<<<dim3(256, Bn), 256>>>(state);

    cudaStreamWaitEvent(0, evB, 0);
    scan_kernel<<<dim3(NCH, Bn, 2), 256, SC_TOTF*4>>>(out);
}

// round 14
// speedup vs baseline: 1.0081x; 1.0081x over previous
#include <cuda_runtime.h>
#include <cuda_bf16.h>

// Problem constants
#define Bn 8
#define Tn 1024
#define Fn 512
#define Dn 64
#define ROWS (Bn*Tn)       // 8192
#define TC 16              // scan chunk length
#define NCH 64             // scan chunks (Tn/TC)

// GEMM tiling
#define MBLK 64            // rows per block
#define NTOT 192           // total W rows (K|Q|V)
#define NKC2 8             // K chunks of 64
#define LDB2 144           // smem row stride bytes (64 bf16 = 128B + 16 pad)
#define OUTS 68            // Q epilogue fp32 tile stride
#define OUTS2 132          // KV epilogue fp32 tile stride (128 + 4)

// Q-GEMM smem (N=64): 2 stages of {A_hi,A_lo,B_hi,B_lo} 64 rows x 144B
#define SA_HI 0
#define SA_LO 9216
#define SB_HI 18432
#define SB_LO 27648
#define STGB  36864
#define SM_TOT (2*STGB)    // 73728

// KV-GEMM smem (N=128): 2 stages of {A_hi,A_lo (64r), B_hi,B_lo (128r)}
#define FA_HI 0
#define FA_LO 9216
#define FB_HI 18432
#define FB_LO 36864
#define FSTGB 55296
#define FSM_TOT (2*FSTGB)  // 110592

// Scan smem layout (floats)
#define SC_KC   0                      // [16][32]
#define SC_QC   (SC_KC + TC*32)        // [16][64]
#define SC_VC   (SC_QC + TC*Dn)        // [16][64]
#define SC_YP   (SC_VC + TC*Dn)        // float4[8][8][8] = 2048 floats
#define SC_TOTF (SC_YP + 8*8*8*4)      // 4608 floats = 18432 B

// Scratch
__device__ float g_K[ROWS*Dn];
__device__ float g_Q[ROWS*Dn];
__device__ float g_V[ROWS*Dn];
__device__ float g_S[Bn*NCH*Dn*Dn];        // 8MB chunk sums
__device__ float g_P[Bn*NCH*Dn*Dn];        // 8MB chunk-prefix states
__device__ unsigned short g_Whi[NTOT*Fn];
__device__ unsigned short g_Wlo[NTOT*Fn];
__device__ unsigned short g_Xhi[ROWS*Fn];
__device__ unsigned short g_Xlo[ROWS*Fn];

__device__ __forceinline__ unsigned smem_u32(const void* p){
    unsigned a;
    asm("{ .reg .u64 t; cvta.to.shared.u64 t, %1; cvt.u32.u64 %0, t; }" : "=r"(a) : "l"(p));
    return a;
}
__device__ __forceinline__ void cp16(unsigned dst, const void* src){
    asm volatile("cp.async.cg.shared.global [%0], [%1], 16;" :: "r"(dst), "l"(src));
}
#define CP_COMMIT() asm volatile("cp.async.commit_group;" ::: "memory")
#define CP_WAIT(n)  asm volatile("cp.async.wait_group %0;" :: "n"(n) : "memory")

#define LDSM4(r, addr) \
    asm volatile("ldmatrix.sync.aligned.m8n8.x4.shared.b16 {%0,%1,%2,%3}, [%4];" \
        : "=r"((r)[0]), "=r"((r)[1]), "=r"((r)[2]), "=r"((r)[3]) : "r"(addr))

#define MMA_BF16(d, a, b0, b1) \
    asm volatile("mma.sync.aligned.m16n8k16.row.col.f32.bf16.bf16.f32 " \
        "{%0,%1,%2,%3}, {%4,%5,%6,%7}, {%8,%9}, {%0,%1,%2,%3};" \
        : "+f"((d)[0]), "+f"((d)[1]), "+f"((d)[2]), "+f"((d)[3]) \
        : "r"((a)[0]), "r"((a)[1]), "r"((a)[2]), "r"((a)[3]), "r"(b0), "r"(b1))

__device__ __forceinline__ unsigned pack_bf2(float v0, float v1, unsigned short* lo0, unsigned short* lo1){
    __nv_bfloat16 h0 = __float2bfloat16(v0);
    __nv_bfloat16 h1 = __float2bfloat16(v1);
    *lo0 = __bfloat16_as_ushort(__float2bfloat16(v0 - __bfloat162float(h0)));
    *lo1 = __bfloat16_as_ushort(__float2bfloat16(v1 - __bfloat162float(h1)));
    return (unsigned)__bfloat16_as_ushort(h0) | ((unsigned)__bfloat16_as_ushort(h1) << 16);
}

// ---------------------------------------------------------------------------
// Fused prep: blocks [0,256) = LN+split x ; blocks [256,448) = W transpose+split
// ---------------------------------------------------------------------------
__global__ void __launch_bounds__(256) prep_kernel(
    const float* __restrict__ x,
    const float* __restrict__ Wk, const float* __restrict__ Wq,
    const float* __restrict__ Wv,
    const float* __restrict__ gamma, const float* __restrict__ beta)
{
    if (blockIdx.x >= 256) {
        const int n = blockIdx.x - 256;
        const int m = n >> 6, j = n & 63;
        const float* W = (m == 0) ? Wk : ((m == 1) ? Wq : Wv);
        const int k0 = threadIdx.x * 2;
        float v0 = __ldg(W + (size_t)k0*Dn + j);
        float v1 = __ldg(W + (size_t)(k0+1)*Dn + j);
        unsigned short l0, l1;
        unsigned hi = pack_bf2(v0, v1, &l0, &l1);
        unsigned lo = (unsigned)l0 | ((unsigned)l1 << 16);
        reinterpret_cast<unsigned*>(g_Whi)[n*(Fn/2) + threadIdx.x] = hi;
        reinterpret_cast<unsigned*>(g_Wlo)[n*(Fn/2) + threadIdx.x] = lo;
        return;
    }
    const int w = threadIdx.x >> 5, l = threadIdx.x & 31;
#pragma unroll 1
    for (int rr = 0; rr < 4; rr++) {
        const int row = blockIdx.x*32 + w*4 + rr;
        const float4* xr = reinterpret_cast<const float4*>(x + (size_t)row * Fn);
        float4 v[4];
        float s = 0.f, ss = 0.f;
#pragma unroll
        for (int q = 0; q < 4; q++) {
            v[q] = xr[q*32 + l];
            s  += v[q].x + v[q].y + v[q].z + v[q].w;
            ss += v[q].x*v[q].x + v[q].y*v[q].y + v[q].z*v[q].z + v[q].w*v[q].w;
        }
#pragma unroll
        for (int o = 16; o; o >>= 1) {
            s  += __shfl_xor_sync(0xffffffffu, s,  o);
            ss += __shfl_xor_sync(0xffffffffu, ss, o);
        }
        const float mu   = s * (1.f/512.f);
        const float var  = ss * (1.f/512.f) - mu*mu;
        const float rstd = rsqrtf(var + 1e-5f);
#pragma unroll
        for (int q = 0; q < 4; q++) {
            const int c4 = q*32 + l;
            float4 g4 = __ldg(reinterpret_cast<const float4*>(gamma) + c4);
            float4 b4 = __ldg(reinterpret_cast<const float4*>(beta)  + c4);
            float vv[4] = {v[q].x, v[q].y, v[q].z, v[q].w};
            float gg[4] = {g4.x, g4.y, g4.z, g4.w};
            float bb[4] = {b4.x, b4.y, b4.z, b4.w};
#pragma unroll
            for (int e = 0; e < 4; e++) vv[e] = (vv[e] - mu)*rstd*gg[e] + bb[e];
            unsigned short s0, s1, s2, s3;
            unsigned h0 = pack_bf2(vv[0], vv[1], &s0, &s1);
            unsigned h1 = pack_bf2(vv[2], vv[3], &s2, &s3);
            unsigned lo0 = (unsigned)s0 | ((unsigned)s1 << 16);
            unsigned lo1 = (unsigned)s2 | ((unsigned)s3 << 16);
            *reinterpret_cast<uint2*>(g_Xhi + (size_t)row*Fn + c4*4) = make_uint2(h0, h1);
            *reinterpret_cast<uint2*>(g_Xlo + (size_t)row*Fn + c4*4) = make_uint2(lo0, lo1);
        }
    }
}

// ---------------------------------------------------------------------------
// Fused KV-GEMM + chunk-sum. grid 128, 256 threads (8 warps: 2M x 4N(32)).
// ---------------------------------------------------------------------------
__global__ void __launch_bounds__(256) gemm_kv_kernel()
{
    extern __shared__ char smem[];
    const int tid = threadIdx.x, w = tid >> 5, l = tid & 31;
    const int mb = blockIdx.x;
    const int row0 = mb * MBLK;
    const unsigned sbase = smem_u32(smem);
    const int wm = w & 1, wn = w >> 1;

    const int sr = tid >> 2, seg = tid & 3;
    const char* srcAh = (const char*)(g_Xhi + (size_t)(row0 + sr)*Fn) + seg*32;
    const char* srcAl = (const char*)(g_Xlo + (size_t)(row0 + sr)*Fn) + seg*32;
    const char* srcB0h = (const char*)(g_Whi + (size_t)sr*Fn) + seg*32;
    const char* srcB0l = (const char*)(g_Wlo + (size_t)sr*Fn) + seg*32;
    const char* srcB1h = (const char*)(g_Whi + (size_t)(128 + sr)*Fn) + seg*32;
    const char* srcB1l = (const char*)(g_Wlo + (size_t)(128 + sr)*Fn) + seg*32;
    const unsigned dA  = sbase + (unsigned)sr*LDB2 + seg*32;
    const unsigned dB0 = sbase + (unsigned)sr*LDB2 + seg*32;
    const unsigned dB1 = sbase + (unsigned)(64 + sr)*LDB2 + seg*32;

    unsigned a_off[2], b_off[2];
#pragma unroll
    for (int mt = 0; mt < 2; mt++)
        a_off[mt] = sbase + FA_HI + (unsigned)(wm*32 + mt*16 + (l & 15))*LDB2 + ((l >> 4) << 4);
#pragma unroll
    for (int bb = 0; bb < 2; bb++)
        b_off[bb] = sbase + FB_HI
            + (unsigned)(wn*32 + bb*16 + ((l >> 4) << 3) + (l & 7))*LDB2 + (((l >> 3) & 1) << 4);

    float acc[2][4][4];
#pragma unroll
    for (int mt = 0; mt < 2; mt++)
#pragma unroll
        for (int nt = 0; nt < 4; nt++)
#pragma unroll
            for (int e = 0; e < 4; e++) acc[mt][nt][e] = 0.f;

    {
        cp16(dA + FA_HI, srcAh);   cp16(dA + FA_HI + 16, srcAh + 16);
        cp16(dA + FA_LO, srcAl);   cp16(dA + FA_LO + 16, srcAl + 16);
        cp16(dB0 + FB_HI, srcB0h); cp16(dB0 + FB_HI + 16, srcB0h + 16);
        cp16(dB0 + FB_LO, srcB0l); cp16(dB0 + FB_LO + 16, srcB0l + 16);
        cp16(dB1 + FB_HI, srcB1h); cp16(dB1 + FB_HI + 16, srcB1h + 16);
        cp16(dB1 + FB_LO, srcB1l); cp16(dB1 + FB_LO + 16, srcB1l + 16);
        CP_COMMIT();
    }

#pragma unroll 1
    for (int c = 0; c < NKC2; c++) {
        if (c < NKC2 - 1) {
            const unsigned st = ((c + 1) & 1)*FSTGB;
            const int o = (c + 1)*128;
            cp16(dA + st + FA_HI, srcAh + o);   cp16(dA + st + FA_HI + 16, srcAh + o + 16);
            cp16(dA + st + FA_LO, srcAl + o);   cp16(dA + st + FA_LO + 16, srcAl + o + 16);
            cp16(dB0 + st + FB_HI, srcB0h + o); cp16(dB0 + st + FB_HI + 16, srcB0h + o + 16);
            cp16(dB0 + st + FB_LO, srcB0l + o); cp16(dB0 + st + FB_LO + 16, srcB0l + o + 16);
            cp16(dB1 + st + FB_HI, srcB1h + o); cp16(dB1 + st + FB_HI + 16, srcB1h + o + 16);
            cp16(dB1 + st + FB_LO, srcB1l + o); cp16(dB1 + st + FB_LO + 16, srcB1l + o + 16);
            CP_COMMIT();
            CP_WAIT(1);
        } else {
            CP_WAIT(0);
        }
        __syncthreads();

        const unsigned so = (unsigned)(c & 1)*FSTGB;
#pragma unroll
        for (int ks = 0; ks < 4; ks++) {
            const unsigned koff = so + ks*32;
            unsigned ahi[2][4], alo[2][4], bhi[2][4], blo[2][4];
#pragma unroll
            for (int mt = 0; mt < 2; mt++) {
                LDSM4(ahi[mt], a_off[mt] + koff);
                LDSM4(alo[mt], a_off[mt] + koff + (FA_LO - FA_HI));
            }
#pragma unroll
            for (int bb = 0; bb < 2; bb++) {
                LDSM4(bhi[bb], b_off[bb] + koff);
                LDSM4(blo[bb], b_off[bb] + koff + (FB_LO - FB_HI));
            }
#pragma unroll
            for (int mt = 0; mt < 2; mt++)
#pragma unroll
                for (int nt = 0; nt < 4; nt++) {
                    const int p = nt >> 1, h = (nt & 1)*2;
                    MMA_BF16(acc[mt][nt], ahi[mt], bhi[p][h], bhi[p][h+1]);
                    MMA_BF16(acc[mt][nt], ahi[mt], blo[p][h], blo[p][h+1]);
                    MMA_BF16(acc[mt][nt], alo[mt], bhi[p][h], bhi[p][h+1]);
                }
        }
        __syncthreads();
    }

    float* outt = reinterpret_cast<float*>(smem);
#pragma unroll
    for (int mt = 0; mt < 2; mt++)
#pragma unroll
        for (int nt = 0; nt < 4; nt++) {
            const int r   = wm*32 + mt*16 + (l >> 2);
            const int col = wn*32 + nt*8 + (l & 3)*2;
            *reinterpret_cast<float2*>(&outt[r*OUTS2 + col])     = make_float2(acc[mt][nt][0], acc[mt][nt][1]);
            *reinterpret_cast<float2*>(&outt[(r+8)*OUTS2 + col]) = make_float2(acc[mt][nt][2], acc[mt][nt][3]);
        }
    __syncthreads();

#pragma unroll 1
    for (int r8 = 0; r8 < 8; r8++) {
        const int r = w*8 + r8;
        const int grow = row0 + r;
        float k0 = fmaxf(outt[r*OUTS2 + l], 0.f);
        float k1 = fmaxf(outt[r*OUTS2 + 32 + l], 0.f);
        float s = k0 + k1;
#pragma unroll
        for (int o = 16; o; o >>= 1) s += __shfl_xor_sync(0xffffffffu, s, o);
        const float rs = 1.f / (1e-5f + s);
        k0 *= rs; k1 *= rs;
        outt[r*OUTS2 + l]      = k0;
        outt[r*OUTS2 + 32 + l] = k1;
        g_K[(size_t)grow*Dn + l]      = k0;
        g_K[(size_t)grow*Dn + 32 + l] = k1;
        g_V[(size_t)grow*Dn + l]      = outt[r*OUTS2 + 64 + l];
        g_V[(size_t)grow*Dn + 32 + l] = outt[r*OUTS2 + 96 + l];
    }
    __syncthreads();

    const int jg = tid & 15, ig = tid >> 4;
#pragma unroll 1
    for (int ch = 0; ch < 4; ch++) {
        float a4[4][4] = {};
#pragma unroll
        for (int t = 0; t < TC; t++) {
            const int row = ch*16 + t;
            float4 k4 = *reinterpret_cast<const float4*>(&outt[row*OUTS2 + jg*4]);
            float4 v4 = *reinterpret_cast<const float4*>(&outt[row*OUTS2 + 64 + ig*4]);
            float kk[4] = {k4.x, k4.y, k4.z, k4.w};
            float vv[4] = {v4.x, v4.y, v4.z, v4.w};
#pragma unroll
            for (int i = 0; i < 4; i++)
#pragma unroll
                for (int j = 0; j < 4; j++) a4[i][j] += vv[i]*kk[j];
        }
        float* S = g_S + (size_t)(mb*4 + ch)*(Dn*Dn);
#pragma unroll
        for (int i = 0; i < 4; i++)
            *reinterpret_cast<float4*>(S + (ig*4 + i)*Dn + jg*4) =
                make_float4(a4[i][0], a4[i][1], a4[i][2], a4[i][3]);
    }
}

// ---------------------------------------------------------------------------
// Q-GEMM: grid 128, 256 threads (8 warps: 2M x 4N(16)), cp.async 2-stage.
// ---------------------------------------------------------------------------
__global__ void __launch_bounds__(256) gemm_q_kernel()
{
    extern __shared__ char smem[];
    const int tid = threadIdx.x, w = tid >> 5, l = tid & 31;
    const int mb = blockIdx.x;
    const int row0 = mb * MBLK;
    const unsigned sbase = smem_u32(smem);
    const int wm = w & 1, wn = w >> 1;

    const int sr = tid >> 2, seg = tid & 3;
    const char* srcAh = (const char*)(g_Xhi + (size_t)(row0 + sr)*Fn) + seg*32;
    const char* srcAl = (const char*)(g_Xlo + (size_t)(row0 + sr)*Fn) + seg*32;
    const char* srcBh = (const char*)(g_Whi + (size_t)(64 + sr)*Fn) + seg*32;
    const char* srcBl = (const char*)(g_Wlo + (size_t)(64 + sr)*Fn) + seg*32;
    const unsigned dbase = sbase + (unsigned)sr*LDB2 + seg*32;

    unsigned a_off[2];
#pragma unroll
    for (int mt = 0; mt < 2; mt++)
        a_off[mt] = sbase + SA_HI + (unsigned)(wm*32 + mt*16 + (l & 15))*LDB2 + ((l >> 4) << 4);
    const unsigned b_off = sbase + SB_HI
        + (unsigned)(wn*16 + ((l >> 4) << 3) + (l & 7))*LDB2 + (((l >> 3) & 1) << 4);

    float acc[2][2][4];
#pragma unroll
    for (int mt = 0; mt < 2; mt++)
#pragma unroll
        for (int nt = 0; nt < 2; nt++)
#pragma unroll
            for (int e = 0; e < 4; e++) acc[mt][nt][e] = 0.f;

    {
        const unsigned d = dbase;
        cp16(d + SA_HI, srcAh);  cp16(d + SA_HI + 16, srcAh + 16);
        cp16(d + SA_LO, srcAl);  cp16(d + SA_LO + 16, srcAl + 16);
        cp16(d + SB_HI, srcBh);  cp16(d + SB_HI + 16, srcBh + 16);
        cp16(d + SB_LO, srcBl);  cp16(d + SB_LO + 16, srcBl + 16);
        CP_COMMIT();
    }

#pragma unroll 1
    for (int c = 0; c < NKC2; c++) {
        if (c < NKC2 - 1) {
            const unsigned d = dbase + ((c + 1) & 1)*STGB;
            const int o = (c + 1)*128;
            cp16(d + SA_HI, srcAh + o);  cp16(d + SA_HI + 16, srcAh + o + 16);
            cp16(d + SA_LO, srcAl + o);  cp16(d + SA_LO + 16, srcAl + o + 16);
            cp16(d + SB_HI, srcBh + o);  cp16(d + SB_HI + 16, srcBh + o + 16);
            cp16(d + SB_LO, srcBl + o);  cp16(d + SB_LO + 16, srcBl + o + 16);
            CP_COMMIT();
            CP_WAIT(1);
        } else {
            CP_WAIT(0);
        }
        __syncthreads();

        const unsigned so = (unsigned)(c & 1)*STGB;
#pragma unroll
        for (int ks = 0; ks < 4; ks++) {
            const unsigned koff = so + ks*32;
            unsigned ahi[2][4], alo[2][4], bhi[4], blo[4];
#pragma unroll
            for (int mt = 0; mt < 2; mt++) {
                LDSM4(ahi[mt], a_off[mt] + koff);
                LDSM4(alo[mt], a_off[mt] + koff + (SA_LO - SA_HI));
            }
            LDSM4(bhi, b_off + koff);
            LDSM4(blo, b_off + koff + (SB_LO - SB_HI));
#pragma unroll
            for (int mt = 0; mt < 2; mt++)
#pragma unroll
                for (int nt = 0; nt < 2; nt++) {
                    const int h = nt*2;
                    MMA_BF16(acc[mt][nt], ahi[mt], bhi[h], bhi[h+1]);
                    MMA_BF16(acc[mt][nt], ahi[mt], blo[h], blo[h+1]);
                    MMA_BF16(acc[mt][nt], alo[mt], bhi[h], bhi[h+1]);
                }
        }
        __syncthreads();
    }

    float* outt = reinterpret_cast<float*>(smem);
#pragma unroll
    for (int mt = 0; mt < 2; mt++)
#pragma unroll
        for (int nt = 0; nt < 2; nt++) {
            const int r   = wm*32 + mt*16 + (l >> 2);
            const int col = wn*16 + nt*8 + (l & 3)*2;
            *reinterpret_cast<float2*>(&outt[r*OUTS + col])     = make_float2(acc[mt][nt][0], acc[mt][nt][1]);
            *reinterpret_cast<float2*>(&outt[(r+8)*OUTS + col]) = make_float2(acc[mt][nt][2], acc[mt][nt][3]);
        }
    __syncthreads();

#pragma unroll 1
    for (int r8 = 0; r8 < 8; r8++) {
        const int r = w*8 + r8;
        const int grow = row0 + r;
        float v0 = fmaxf(outt[r*OUTS + l], 0.f);
        float v1 = fmaxf(outt[r*OUTS + 32 + l], 0.f);
        float s = v0 + v1;
#pragma unroll
        for (int o = 16; o; o >>= 1) s += __shfl_xor_sync(0xffffffffu, s, o);
        const float rs = 1.f / (1e-5f + s);
        g_Q[(size_t)grow*Dn + l]      = v0 * rs;
        g_Q[(size_t)grow*Dn + 32 + l] = v1 * rs;
    }
}

// ---------------------------------------------------------------------------
// Prefix, smem-staged & coalesced. grid (32, Bn) = 256 blocks, 256 threads.
// Block covers 32 contiguous float4 elements x 64 chunks.
// Phase 1: coalesced load S -> smem (SoA planes, stride 33).
// Phase 2: per element, 2x 32-lane shfl scan over chunks + state base,
//          exclusive values written back to smem.
// Phase 3: coalesced store smem -> P.
// ---------------------------------------------------------------------------
__global__ void __launch_bounds__(256) prefix_kernel(const float* __restrict__ state)
{
    __shared__ float sp[4][NCH][33];
    const int b = blockIdx.y, eb = blockIdx.x;
    const int tid = threadIdx.x, w = tid >> 5, l = tid & 31;

    // Phase 1: load (warp = one chunk's 32 float4 = 512B contiguous)
#pragma unroll
    for (int i = 0; i < 8; i++) {
        const int idx = i*256 + tid;
        const int ch = idx >> 5, el = idx & 31;
        float4 v = *reinterpret_cast<const float4*>(
            g_S + (size_t)(b*NCH + ch)*(Dn*Dn) + (eb*32 + el)*4);
        sp[0][ch][el] = v.x; sp[1][ch][el] = v.y;
        sp[2][ch][el] = v.z; sp[3][ch][el] = v.w;
    }
    __syncthreads();

    // Phase 2: scan. warp w handles elements w*4 .. w*4+3; lane = chunk (2 halves)
#pragma unroll 1
    for (int em = 0; em < 4; em++) {
        const int el = w*4 + em;
        float4 st = __ldg(reinterpret_cast<const float4*>(
            state + (size_t)b*(Dn*Dn) + (eb*32 + el)*4));
        const float stv[4] = {st.x, st.y, st.z, st.w};
#pragma unroll
        for (int p = 0; p < 4; p++) {
            float v0 = sp[p][l][el];
            float v1 = sp[p][l + 32][el];
            float inc0 = v0, inc1 = v1;
#pragma unroll
            for (int o = 1; o < 32; o <<= 1) {
                float a0 = __shfl_up_sync(0xffffffffu, inc0, o);
                float a1 = __shfl_up_sync(0xffffffffu, inc1, o);
                if (l >= o) { inc0 += a0; inc1 += a1; }
            }
            const float t0 = __shfl_sync(0xffffffffu, inc0, 31);
            sp[p][l][el]      = stv[p] + (inc0 - v0);
            sp[p][l + 32][el] = stv[p] + t0 + (inc1 - v1);
        }
    }
    __syncthreads();

    // Phase 3: coalesced store
#pragma unroll
    for (int i = 0; i < 8; i++) {
        const int idx = i*256 + tid;
        const int ch = idx >> 5, el = idx & 31;
        float4 v = make_float4(sp[0][ch][el], sp[1][ch][el],
                               sp[2][ch][el], sp[3][ch][el]);
        *reinterpret_cast<float4*>(
            g_P + (size_t)(b*NCH + ch)*(Dn*Dn) + (eb*32 + el)*4) = v;
    }
}

// ---------------------------------------------------------------------------
// Scan: grid (NCH, Bn, 2 j-halves) = 1024 blocks, 256 threads, TC=16.
// ---------------------------------------------------------------------------
__global__ void __launch_bounds__(256) scan_kernel(float* __restrict__ out)
{
    extern __shared__ float sm[];
    float*  Kc = sm + SC_KC;
    float*  Qc = sm + SC_QC;
    float*  Vc = sm + SC_VC;
    float4* ypbuf = reinterpret_cast<float4*>(sm + SC_YP);

    const int c = blockIdx.x, b = blockIdx.y, jh = blockIdx.z;
    const int tid = threadIdx.x, w = tid >> 5, l = tid & 31;
    const int ig = tid >> 3, jg = tid & 7;

    float acc[2][4];
    {
        const float* P = g_P + (size_t)(b*NCH + c)*(Dn*Dn) + jh*32 + jg*4;
#pragma unroll
        for (int i = 0; i < 2; i++) {
            float4 p = *reinterpret_cast<const float4*>(P + (ig*2 + i)*Dn);
            acc[i][0] = p.x; acc[i][1] = p.y; acc[i][2] = p.z; acc[i][3] = p.w;
        }
    }

    {
        const int base = (b*Tn + c*TC) * Dn;
        if (tid < 128) {
            const int t = tid >> 3, jj = (tid & 7)*4;
            *reinterpret_cast<float4*>(Kc + t*32 + jj) =
                *reinterpret_cast<const float4*>(g_K + base + t*Dn + jh*32 + jj);
        }
        {
            const int t = tid >> 4, jj = (tid & 15)*4;
            *reinterpret_cast<float4*>(Qc + t*Dn + jj) =
                *reinterpret_cast<const float4*>(g_Q + base + t*Dn + jj);
            *reinterpret_cast<float4*>(Vc + t*Dn + jj) =
                *reinterpret_cast<const float4*>(g_V + base + t*Dn + jj);
        }
    }
    __syncthreads();

    float* yout = out;
    float* sout = out + (size_t)ROWS * Dn;
    const int rbase0 = b*Tn + c*TC;

#pragma unroll 1
    for (int tg = 0; tg < TC/8; tg++) {
#pragma unroll
        for (int tt = 0; tt < 8; tt++) {
            const int t = tg*8 + tt;
            float4 k4 = *reinterpret_cast<const float4*>(Kc + t*32 + jg*4);
            float2 q2 = *reinterpret_cast<const float2*>(Qc + t*Dn + ig*2);
            float2 v2 = *reinterpret_cast<const float2*>(Vc + t*Dn + ig*2);
            const float kk[4] = {k4.x, k4.y, k4.z, k4.w};
            float yp[4] = {0.f, 0.f, 0.f, 0.f};
            float* srow = sout + (size_t)(rbase0 + t)*(Dn*Dn) + jh*32 + jg*4;

#pragma unroll
            for (int e = 0; e < 4; e++) { acc[0][e] += v2.x*kk[e]; yp[e] += acc[0][e]*q2.x; }
            __stcs(reinterpret_cast<float4*>(srow + (ig*2)*Dn),
                   make_float4(acc[0][0], acc[0][1], acc[0][2], acc[0][3]));
#pragma unroll
            for (int e = 0; e < 4; e++) { acc[1][e] += v2.y*kk[e]; yp[e] += acc[1][e]*q2.y; }
            __stcs(reinterpret_cast<float4*>(srow + (ig*2 + 1)*Dn),
                   make_float4(acc[1][0], acc[1][1], acc[1][2], acc[1][3]));

#pragma unroll
            for (int e = 0; e < 4; e++) {
                yp[e] += __shfl_xor_sync(0xffffffffu, yp[e], 8);
                yp[e] += __shfl_xor_sync(0xffffffffu, yp[e], 16);
            }
            if (l < 8) ypbuf[(tt*8 + w)*8 + l] = make_float4(yp[0], yp[1], yp[2], yp[3]);
        }
        __syncthreads();
        if (tid < 64) {
            const int tt = tid >> 3, jp = tid & 7;
            float4 s = make_float4(0.f, 0.f, 0.f, 0.f);
#pragma unroll
            for (int w8 = 0; w8 < 8; w8++) {
                float4 v = ypbuf[(tt*8 + w8)*8 + jp];
                s.x += v.x; s.y += v.y; s.z += v.z; s.w += v.w;
            }
            __stcs(reinterpret_cast<float4*>(
                yout + (size_t)(rbase0 + tg*8 + tt)*Dn + jh*32 + jp*4), s);
        }
        __syncthreads();
    }
}

// ---------------------------------------------------------------------------
extern "C" void kernel_launch(void* const* d_in, const int* in_sizes, int n_in,
                              void* d_out, int out_size)
{
    const float* x     = (const float*)d_in[0];
    const float* state = (const float*)d_in[1];
    const float* Wk    = (const float*)d_in[2];
    const float* Wq    = (const float*)d_in[3];
    const float* Wv    = (const float*)d_in[4];
    const float* gamma = (const float*)d_in[5];
    const float* beta  = (const float*)d_in[6];
    float* out = (float*)d_out;

    static cudaStream_t s1 = nullptr;
    static cudaEvent_t evA = nullptr, evB = nullptr;
    if (s1 == nullptr) {
        cudaStreamCreateWithFlags(&s1, cudaStreamNonBlocking);
        cudaEventCreateWithFlags(&evA, cudaEventDisableTiming);
        cudaEventCreateWithFlags(&evB, cudaEventDisableTiming);
        cudaFuncSetAttribute(gemm_kv_kernel, cudaFuncAttributeMaxDynamicSharedMemorySize, FSM_TOT);
        cudaFuncSetAttribute(gemm_q_kernel,  cudaFuncAttributeMaxDynamicSharedMemorySize, SM_TOT);
        cudaFuncSetAttribute(scan_kernel,    cudaFuncAttributeMaxDynamicSharedMemorySize, SC_TOTF*4);
    }

    prep_kernel<<<256 + NTOT, 256>>>(x, Wk, Wq, Wv, gamma, beta);
    cudaEventRecord(evA, 0);

    cudaStreamWaitEvent(s1, evA, 0);
    gemm_q_kernel<<<ROWS/MBLK, 256, SM_TOT, s1>>>();
    cudaEventRecord(evB, s1);

    gemm_kv_kernel<<<ROWS/MBLK, 256, FSM_TOT>>>();
    prefix_kernel<<<dim3(32, Bn), 256>>>(state);

    cudaStreamWaitEvent(0, evB, 0);
    scan_kernel<<<dim3(NCH, Bn, 2), 256, SC_TOTF*4>>>(out);
}

// round 15
// speedup vs baseline: 1.0298x; 1.0216x over previous
#include <cuda_runtime.h>
#include <cuda_bf16.h>

// Problem constants
#define Bn 8
#define Tn 1024
#define Fn 512
#define Dn 64
#define ROWS (Bn*Tn)       // 8192
#define TC 16              // scan chunk length
#define NCH 64             // scan chunks (Tn/TC)

// GEMM tiling
#define MBLK 64            // rows per block
#define NTOT 192           // total W rows (K|Q|V)
#define NKC2 8             // K chunks of 64
#define LDB2 144           // smem row stride bytes (64 bf16 = 128B + 16 pad)
#define OUTS 68            // Q epilogue fp32 tile stride
#define OUTS2 132          // KV epilogue fp32 tile stride (128 + 4)

// Q-GEMM smem (N=64): 2 stages of {A_hi,A_lo,B_hi,B_lo} 64 rows x 144B
#define SA_HI 0
#define SA_LO 9216
#define SB_HI 18432
#define SB_LO 27648
#define STGB  36864
#define SM_TOT (2*STGB)    // 73728

// KV-GEMM smem (N=128): 2 stages of {A_hi,A_lo (64r), B_hi,B_lo (128r)}
#define FA_HI 0
#define FA_LO 9216
#define FB_HI 18432
#define FB_LO 36864
#define FSTGB 55296
#define FSM_TOT (2*FSTGB)  // 110592

// Scan smem layout (floats)
#define SC_KC   0                      // [16][32]
#define SC_QC   (SC_KC + TC*32)        // [16][64]
#define SC_VC   (SC_QC + TC*Dn)        // [16][64]
#define SC_YP   (SC_VC + TC*Dn)        // float4[8][8][8] = 2048 floats
#define SC_TOTF (SC_YP + 8*8*8*4)      // 4608 floats = 18432 B

// Scratch
__device__ float g_K[ROWS*Dn];
__device__ float g_Q[ROWS*Dn];
__device__ float g_V[ROWS*Dn];
__device__ float g_S[Bn*NCH*Dn*Dn];        // 8MB chunk sums
__device__ float g_P[Bn*NCH*Dn*Dn];        // 8MB chunk-prefix states
__device__ unsigned short g_Whi[NTOT*Fn];
__device__ unsigned short g_Wlo[NTOT*Fn];
__device__ unsigned short g_Xhi[ROWS*Fn];
__device__ unsigned short g_Xlo[ROWS*Fn];

__device__ __forceinline__ unsigned smem_u32(const void* p){
    unsigned a;
    asm("{ .reg .u64 t; cvta.to.shared.u64 t, %1; cvt.u32.u64 %0, t; }" : "=r"(a) : "l"(p));
    return a;
}
__device__ __forceinline__ void cp16(unsigned dst, const void* src){
    asm volatile("cp.async.cg.shared.global [%0], [%1], 16;" :: "r"(dst), "l"(src));
}
#define CP_COMMIT() asm volatile("cp.async.commit_group;" ::: "memory")
#define CP_WAIT(n)  asm volatile("cp.async.wait_group %0;" :: "n"(n) : "memory")

#define LDSM4(r, addr) \
    asm volatile("ldmatrix.sync.aligned.m8n8.x4.shared.b16 {%0,%1,%2,%3}, [%4];" \
        : "=r"((r)[0]), "=r"((r)[1]), "=r"((r)[2]), "=r"((r)[3]) : "r"(addr))

#define MMA_BF16(d, a, b0, b1) \
    asm volatile("mma.sync.aligned.m16n8k16.row.col.f32.bf16.bf16.f32 " \
        "{%0,%1,%2,%3}, {%4,%5,%6,%7}, {%8,%9}, {%0,%1,%2,%3};" \
        : "+f"((d)[0]), "+f"((d)[1]), "+f"((d)[2]), "+f"((d)[3]) \
        : "r"((a)[0]), "r"((a)[1]), "r"((a)[2]), "r"((a)[3]), "r"(b0), "r"(b1))

__device__ __forceinline__ unsigned pack_bf2(float v0, float v1, unsigned short* lo0, unsigned short* lo1){
    __nv_bfloat16 h0 = __float2bfloat16(v0);
    __nv_bfloat16 h1 = __float2bfloat16(v1);
    *lo0 = __bfloat16_as_ushort(__float2bfloat16(v0 - __bfloat162float(h0)));
    *lo1 = __bfloat16_as_ushort(__float2bfloat16(v1 - __bfloat162float(h1)));
    return (unsigned)__bfloat16_as_ushort(h0) | ((unsigned)__bfloat16_as_ushort(h1) << 16);
}

// ---------------------------------------------------------------------------
// Fused prep: blocks [0,256) = LN+split x ; blocks [256,448) = W transpose+split
// ---------------------------------------------------------------------------
__global__ void __launch_bounds__(256) prep_kernel(
    const float* __restrict__ x,
    const float* __restrict__ Wk, const float* __restrict__ Wq,
    const float* __restrict__ Wv,
    const float* __restrict__ gamma, const float* __restrict__ beta)
{
    if (blockIdx.x >= 256) {
        const int n = blockIdx.x - 256;
        const int m = n >> 6, j = n & 63;
        const float* W = (m == 0) ? Wk : ((m == 1) ? Wq : Wv);
        const int k0 = threadIdx.x * 2;
        float v0 = __ldg(W + (size_t)k0*Dn + j);
        float v1 = __ldg(W + (size_t)(k0+1)*Dn + j);
        unsigned short l0, l1;
        unsigned hi = pack_bf2(v0, v1, &l0, &l1);
        unsigned lo = (unsigned)l0 | ((unsigned)l1 << 16);
        reinterpret_cast<unsigned*>(g_Whi)[n*(Fn/2) + threadIdx.x] = hi;
        reinterpret_cast<unsigned*>(g_Wlo)[n*(Fn/2) + threadIdx.x] = lo;
        return;
    }
    const int w = threadIdx.x >> 5, l = threadIdx.x & 31;
#pragma unroll 1
    for (int rr = 0; rr < 4; rr++) {
        const int row = blockIdx.x*32 + w*4 + rr;
        const float4* xr = reinterpret_cast<const float4*>(x + (size_t)row * Fn);
        float4 v[4];
        float s = 0.f, ss = 0.f;
#pragma unroll
        for (int q = 0; q < 4; q++) {
            v[q] = xr[q*32 + l];
            s  += v[q].x + v[q].y + v[q].z + v[q].w;
            ss += v[q].x*v[q].x + v[q].y*v[q].y + v[q].z*v[q].z + v[q].w*v[q].w;
        }
#pragma unroll
        for (int o = 16; o; o >>= 1) {
            s  += __shfl_xor_sync(0xffffffffu, s,  o);
            ss += __shfl_xor_sync(0xffffffffu, ss, o);
        }
        const float mu   = s * (1.f/512.f);
        const float var  = ss * (1.f/512.f) - mu*mu;
        const float rstd = rsqrtf(var + 1e-5f);
#pragma unroll
        for (int q = 0; q < 4; q++) {
            const int c4 = q*32 + l;
            float4 g4 = __ldg(reinterpret_cast<const float4*>(gamma) + c4);
            float4 b4 = __ldg(reinterpret_cast<const float4*>(beta)  + c4);
            float vv[4] = {v[q].x, v[q].y, v[q].z, v[q].w};
            float gg[4] = {g4.x, g4.y, g4.z, g4.w};
            float bb[4] = {b4.x, b4.y, b4.z, b4.w};
#pragma unroll
            for (int e = 0; e < 4; e++) vv[e] = (vv[e] - mu)*rstd*gg[e] + bb[e];
            unsigned short s0, s1, s2, s3;
            unsigned h0 = pack_bf2(vv[0], vv[1], &s0, &s1);
            unsigned h1 = pack_bf2(vv[2], vv[3], &s2, &s3);
            unsigned lo0 = (unsigned)s0 | ((unsigned)s1 << 16);
            unsigned lo1 = (unsigned)s2 | ((unsigned)s3 << 16);
            *reinterpret_cast<uint2*>(g_Xhi + (size_t)row*Fn + c4*4) = make_uint2(h0, h1);
            *reinterpret_cast<uint2*>(g_Xlo + (size_t)row*Fn + c4*4) = make_uint2(lo0, lo1);
        }
    }
}

// ---------------------------------------------------------------------------
// Fused KV-GEMM + chunk-sum. grid 128, 256 threads (8 warps: 2M x 4N(32)).
// ---------------------------------------------------------------------------
__global__ void __launch_bounds__(256) gemm_kv_kernel()
{
    extern __shared__ char smem[];
    const int tid = threadIdx.x, w = tid >> 5, l = tid & 31;
    const int mb = blockIdx.x;
    const int row0 = mb * MBLK;
    const unsigned sbase = smem_u32(smem);
    const int wm = w & 1, wn = w >> 1;

    const int sr = tid >> 2, seg = tid & 3;
    const char* srcAh = (const char*)(g_Xhi + (size_t)(row0 + sr)*Fn) + seg*32;
    const char* srcAl = (const char*)(g_Xlo + (size_t)(row0 + sr)*Fn) + seg*32;
    const char* srcB0h = (const char*)(g_Whi + (size_t)sr*Fn) + seg*32;
    const char* srcB0l = (const char*)(g_Wlo + (size_t)sr*Fn) + seg*32;
    const char* srcB1h = (const char*)(g_Whi + (size_t)(128 + sr)*Fn) + seg*32;
    const char* srcB1l = (const char*)(g_Wlo + (size_t)(128 + sr)*Fn) + seg*32;
    const unsigned dA  = sbase + (unsigned)sr*LDB2 + seg*32;
    const unsigned dB0 = sbase + (unsigned)sr*LDB2 + seg*32;
    const unsigned dB1 = sbase + (unsigned)(64 + sr)*LDB2 + seg*32;

    unsigned a_off[2], b_off[2];
#pragma unroll
    for (int mt = 0; mt < 2; mt++)
        a_off[mt] = sbase + FA_HI + (unsigned)(wm*32 + mt*16 + (l & 15))*LDB2 + ((l >> 4) << 4);
#pragma unroll
    for (int bb = 0; bb < 2; bb++)
        b_off[bb] = sbase + FB_HI
            + (unsigned)(wn*32 + bb*16 + ((l >> 4) << 3) + (l & 7))*LDB2 + (((l >> 3) & 1) << 4);

    float acc[2][4][4];
#pragma unroll
    for (int mt = 0; mt < 2; mt++)
#pragma unroll
        for (int nt = 0; nt < 4; nt++)
#pragma unroll
            for (int e = 0; e < 4; e++) acc[mt][nt][e] = 0.f;

    {
        cp16(dA + FA_HI, srcAh);   cp16(dA + FA_HI + 16, srcAh + 16);
        cp16(dA + FA_LO, srcAl);   cp16(dA + FA_LO + 16, srcAl + 16);
        cp16(dB0 + FB_HI, srcB0h); cp16(dB0 + FB_HI + 16, srcB0h + 16);
        cp16(dB0 + FB_LO, srcB0l); cp16(dB0 + FB_LO + 16, srcB0l + 16);
        cp16(dB1 + FB_HI, srcB1h); cp16(dB1 + FB_HI + 16, srcB1h + 16);
        cp16(dB1 + FB_LO, srcB1l); cp16(dB1 + FB_LO + 16, srcB1l + 16);
        CP_COMMIT();
    }

#pragma unroll 1
    for (int c = 0; c < NKC2; c++) {
        if (c < NKC2 - 1) {
            const unsigned st = ((c + 1) & 1)*FSTGB;
            const int o = (c + 1)*128;
            cp16(dA + st + FA_HI, srcAh + o);   cp16(dA + st + FA_HI + 16, srcAh + o + 16);
            cp16(dA + st + FA_LO, srcAl + o);   cp16(dA + st + FA_LO + 16, srcAl + o + 16);
            cp16(dB0 + st + FB_HI, srcB0h + o); cp16(dB0 + st + FB_HI + 16, srcB0h + o + 16);
            cp16(dB0 + st + FB_LO, srcB0l + o); cp16(dB0 + st + FB_LO + 16, srcB0l + o + 16);
            cp16(dB1 + st + FB_HI, srcB1h + o); cp16(dB1 + st + FB_HI + 16, srcB1h + o + 16);
            cp16(dB1 + st + FB_LO, srcB1l + o); cp16(dB1 + st + FB_LO + 16, srcB1l + o + 16);
            CP_COMMIT();
            CP_WAIT(1);
        } else {
            CP_WAIT(0);
        }
        __syncthreads();

        const unsigned so = (unsigned)(c & 1)*FSTGB;
#pragma unroll
        for (int ks = 0; ks < 4; ks++) {
            const unsigned koff = so + ks*32;
            unsigned ahi[2][4], alo[2][4], bhi[2][4], blo[2][4];
#pragma unroll
            for (int mt = 0; mt < 2; mt++) {
                LDSM4(ahi[mt], a_off[mt] + koff);
                LDSM4(alo[mt], a_off[mt] + koff + (FA_LO - FA_HI));
            }
#pragma unroll
            for (int bb = 0; bb < 2; bb++) {
                LDSM4(bhi[bb], b_off[bb] + koff);
                LDSM4(blo[bb], b_off[bb] + koff + (FB_LO - FB_HI));
            }
#pragma unroll
            for (int mt = 0; mt < 2; mt++)
#pragma unroll
                for (int nt = 0; nt < 4; nt++) {
                    const int p = nt >> 1, h = (nt & 1)*2;
                    MMA_BF16(acc[mt][nt], ahi[mt], bhi[p][h], bhi[p][h+1]);
                    MMA_BF16(acc[mt][nt], ahi[mt], blo[p][h], blo[p][h+1]);
                    MMA_BF16(acc[mt][nt], alo[mt], bhi[p][h], bhi[p][h+1]);
                }
        }
        __syncthreads();
    }

    float* outt = reinterpret_cast<float*>(smem);
#pragma unroll
    for (int mt = 0; mt < 2; mt++)
#pragma unroll
        for (int nt = 0; nt < 4; nt++) {
            const int r   = wm*32 + mt*16 + (l >> 2);
            const int col = wn*32 + nt*8 + (l & 3)*2;
            *reinterpret_cast<float2*>(&outt[r*OUTS2 + col])     = make_float2(acc[mt][nt][0], acc[mt][nt][1]);
            *reinterpret_cast<float2*>(&outt[(r+8)*OUTS2 + col]) = make_float2(acc[mt][nt][2], acc[mt][nt][3]);
        }
    __syncthreads();

#pragma unroll 1
    for (int r8 = 0; r8 < 8; r8++) {
        const int r = w*8 + r8;
        const int grow = row0 + r;
        float k0 = fmaxf(outt[r*OUTS2 + l], 0.f);
        float k1 = fmaxf(outt[r*OUTS2 + 32 + l], 0.f);
        float s = k0 + k1;
#pragma unroll
        for (int o = 16; o; o >>= 1) s += __shfl_xor_sync(0xffffffffu, s, o);
        const float rs = 1.f / (1e-5f + s);
        k0 *= rs; k1 *= rs;
        outt[r*OUTS2 + l]      = k0;
        outt[r*OUTS2 + 32 + l] = k1;
        g_K[(size_t)grow*Dn + l]      = k0;
        g_K[(size_t)grow*Dn + 32 + l] = k1;
        g_V[(size_t)grow*Dn + l]      = outt[r*OUTS2 + 64 + l];
        g_V[(size_t)grow*Dn + 32 + l] = outt[r*OUTS2 + 96 + l];
    }
    __syncthreads();

    const int jg = tid & 15, ig = tid >> 4;
#pragma unroll 1
    for (int ch = 0; ch < 4; ch++) {
        float a4[4][4] = {};
#pragma unroll
        for (int t = 0; t < TC; t++) {
            const int row = ch*16 + t;
            float4 k4 = *reinterpret_cast<const float4*>(&outt[row*OUTS2 + jg*4]);
            float4 v4 = *reinterpret_cast<const float4*>(&outt[row*OUTS2 + 64 + ig*4]);
            float kk[4] = {k4.x, k4.y, k4.z, k4.w};
            float vv[4] = {v4.x, v4.y, v4.z, v4.w};
#pragma unroll
            for (int i = 0; i < 4; i++)
#pragma unroll
                for (int j = 0; j < 4; j++) a4[i][j] += vv[i]*kk[j];
        }
        float* S = g_S + (size_t)(mb*4 + ch)*(Dn*Dn);
#pragma unroll
        for (int i = 0; i < 4; i++)
            *reinterpret_cast<float4*>(S + (ig*4 + i)*Dn + jg*4) =
                make_float4(a4[i][0], a4[i][1], a4[i][2], a4[i][3]);
    }
}

// ---------------------------------------------------------------------------
// Q-GEMM: grid 128, 256 threads (8 warps: 2M x 4N(16)), cp.async 2-stage.
// ---------------------------------------------------------------------------
__global__ void __launch_bounds__(256) gemm_q_kernel()
{
    extern __shared__ char smem[];
    const int tid = threadIdx.x, w = tid >> 5, l = tid & 31;
    const int mb = blockIdx.x;
    const int row0 = mb * MBLK;
    const unsigned sbase = smem_u32(smem);
    const int wm = w & 1, wn = w >> 1;

    const int sr = tid >> 2, seg = tid & 3;
    const char* srcAh = (const char*)(g_Xhi + (size_t)(row0 + sr)*Fn) + seg*32;
    const char* srcAl = (const char*)(g_Xlo + (size_t)(row0 + sr)*Fn) + seg*32;
    const char* srcBh = (const char*)(g_Whi + (size_t)(64 + sr)*Fn) + seg*32;
    const char* srcBl = (const char*)(g_Wlo + (size_t)(64 + sr)*Fn) + seg*32;
    const unsigned dbase = sbase + (unsigned)sr*LDB2 + seg*32;

    unsigned a_off[2];
#pragma unroll
    for (int mt = 0; mt < 2; mt++)
        a_off[mt] = sbase + SA_HI + (unsigned)(wm*32 + mt*16 + (l & 15))*LDB2 + ((l >> 4) << 4);
    const unsigned b_off = sbase + SB_HI
        + (unsigned)(wn*16 + ((l >> 4) << 3) + (l & 7))*LDB2 + (((l >> 3) & 1) << 4);

    float acc[2][2][4];
#pragma unroll
    for (int mt = 0; mt < 2; mt++)
#pragma unroll
        for (int nt = 0; nt < 2; nt++)
#pragma unroll
            for (int e = 0; e < 4; e++) acc[mt][nt][e] = 0.f;

    {
        const unsigned d = dbase;
        cp16(d + SA_HI, srcAh);  cp16(d + SA_HI + 16, srcAh + 16);
        cp16(d + SA_LO, srcAl);  cp16(d + SA_LO + 16, srcAl + 16);
        cp16(d + SB_HI, srcBh);  cp16(d + SB_HI + 16, srcBh + 16);
        cp16(d + SB_LO, srcBl);  cp16(d + SB_LO + 16, srcBl + 16);
        CP_COMMIT();
    }

#pragma unroll 1
    for (int c = 0; c < NKC2; c++) {
        if (c < NKC2 - 1) {
            const unsigned d = dbase + ((c + 1) & 1)*STGB;
            const int o = (c + 1)*128;
            cp16(d + SA_HI, srcAh + o);  cp16(d + SA_HI + 16, srcAh + o + 16);
            cp16(d + SA_LO, srcAl + o);  cp16(d + SA_LO + 16, srcAl + o + 16);
            cp16(d + SB_HI, srcBh + o);  cp16(d + SB_HI + 16, srcBh + o + 16);
            cp16(d + SB_LO, srcBl + o);  cp16(d + SB_LO + 16, srcBl + o + 16);
            CP_COMMIT();
            CP_WAIT(1);
        } else {
            CP_WAIT(0);
        }
        __syncthreads();

        const unsigned so = (unsigned)(c & 1)*STGB;
#pragma unroll
        for (int ks = 0; ks < 4; ks++) {
            const unsigned koff = so + ks*32;
            unsigned ahi[2][4], alo[2][4], bhi[4], blo[4];
#pragma unroll
            for (int mt = 0; mt < 2; mt++) {
                LDSM4(ahi[mt], a_off[mt] + koff);
                LDSM4(alo[mt], a_off[mt] + koff + (SA_LO - SA_HI));
            }
            LDSM4(bhi, b_off + koff);
            LDSM4(blo, b_off + koff + (SB_LO - SB_HI));
#pragma unroll
            for (int mt = 0; mt < 2; mt++)
#pragma unroll
                for (int nt = 0; nt < 2; nt++) {
                    const int h = nt*2;
                    MMA_BF16(acc[mt][nt], ahi[mt], bhi[h], bhi[h+1]);
                    MMA_BF16(acc[mt][nt], ahi[mt], blo[h], blo[h+1]);
                    MMA_BF16(acc[mt][nt], alo[mt], bhi[h], bhi[h+1]);
                }
        }
        __syncthreads();
    }

    float* outt = reinterpret_cast<float*>(smem);
#pragma unroll
    for (int mt = 0; mt < 2; mt++)
#pragma unroll
        for (int nt = 0; nt < 2; nt++) {
            const int r   = wm*32 + mt*16 + (l >> 2);
            const int col = wn*16 + nt*8 + (l & 3)*2;
            *reinterpret_cast<float2*>(&outt[r*OUTS + col])     = make_float2(acc[mt][nt][0], acc[mt][nt][1]);
            *reinterpret_cast<float2*>(&outt[(r+8)*OUTS + col]) = make_float2(acc[mt][nt][2], acc[mt][nt][3]);
        }
    __syncthreads();

#pragma unroll 1
    for (int r8 = 0; r8 < 8; r8++) {
        const int r = w*8 + r8;
        const int grow = row0 + r;
        float v0 = fmaxf(outt[r*OUTS + l], 0.f);
        float v1 = fmaxf(outt[r*OUTS + 32 + l], 0.f);
        float s = v0 + v1;
#pragma unroll
        for (int o = 16; o; o >>= 1) s += __shfl_xor_sync(0xffffffffu, s, o);
        const float rs = 1.f / (1e-5f + s);
        g_Q[(size_t)grow*Dn + l]      = v0 * rs;
        g_Q[(size_t)grow*Dn + 32 + l] = v1 * rs;
    }
}

// ---------------------------------------------------------------------------
// Prefix, smem-staged & coalesced, fine grain.
// grid (128, Bn) = 1024 blocks, 256 threads.
// Block covers 8 contiguous float4 elements x 64 chunks. smem 9.2KB.
// Phase 1: coalesced load S -> smem (warp = 4 chunks x 8 float4, 128B rows).
// Phase 2: warp w owns element w; lane = chunk (two 32-halves + carry).
// Phase 3: coalesced store smem -> P.
// ---------------------------------------------------------------------------
__global__ void __launch_bounds__(256) prefix_kernel(const float* __restrict__ state)
{
    __shared__ float sp[4][NCH][9];
    const int b = blockIdx.y, eb = blockIdx.x;
    const int tid = threadIdx.x, w = tid >> 5, l = tid & 31;

    // Phase 1: load. idx -> (chunk = idx>>3, element = idx&7)
#pragma unroll
    for (int i = 0; i < 2; i++) {
        const int idx = i*256 + tid;
        const int ch = idx >> 3, el = idx & 7;
        float4 v = *reinterpret_cast<const float4*>(
            g_S + (size_t)(b*NCH + ch)*(Dn*Dn) + (eb*8 + el)*4);
        sp[0][ch][el] = v.x; sp[1][ch][el] = v.y;
        sp[2][ch][el] = v.z; sp[3][ch][el] = v.w;
    }
    __syncthreads();

    // Phase 2: scan. warp w handles element w; lane = chunk in each half.
    {
        const int el = w;
        float4 st = __ldg(reinterpret_cast<const float4*>(
            state + (size_t)b*(Dn*Dn) + (eb*8 + el)*4));
        const float stv[4] = {st.x, st.y, st.z, st.w};
#pragma unroll
        for (int p = 0; p < 4; p++) {
            float v0 = sp[p][l][el];
            float v1 = sp[p][l + 32][el];
            float inc0 = v0, inc1 = v1;
#pragma unroll
            for (int o = 1; o < 32; o <<= 1) {
                float a0 = __shfl_up_sync(0xffffffffu, inc0, o);
                float a1 = __shfl_up_sync(0xffffffffu, inc1, o);
                if (l >= o) { inc0 += a0; inc1 += a1; }
            }
            const float t0 = __shfl_sync(0xffffffffu, inc0, 31);
            sp[p][l][el]      = stv[p] + (inc0 - v0);
            sp[p][l + 32][el] = stv[p] + t0 + (inc1 - v1);
        }
    }
    __syncthreads();

    // Phase 3: coalesced store
#pragma unroll
    for (int i = 0; i < 2; i++) {
        const int idx = i*256 + tid;
        const int ch = idx >> 3, el = idx & 7;
        float4 v = make_float4(sp[0][ch][el], sp[1][ch][el],
                               sp[2][ch][el], sp[3][ch][el]);
        *reinterpret_cast<float4*>(
            g_P + (size_t)(b*NCH + ch)*(Dn*Dn) + (eb*8 + el)*4) = v;
    }
}

// ---------------------------------------------------------------------------
// Scan: grid (NCH, Bn, 2 j-halves) = 1024 blocks, 256 threads, TC=16.
// ---------------------------------------------------------------------------
__global__ void __launch_bounds__(256) scan_kernel(float* __restrict__ out)
{
    extern __shared__ float sm[];
    float*  Kc = sm + SC_KC;
    float*  Qc = sm + SC_QC;
    float*  Vc = sm + SC_VC;
    float4* ypbuf = reinterpret_cast<float4*>(sm + SC_YP);

    const int c = blockIdx.x, b = blockIdx.y, jh = blockIdx.z;
    const int tid = threadIdx.x, w = tid >> 5, l = tid & 31;
    const int ig = tid >> 3, jg = tid & 7;

    float acc[2][4];
    {
        const float* P = g_P + (size_t)(b*NCH + c)*(Dn*Dn) + jh*32 + jg*4;
#pragma unroll
        for (int i = 0; i < 2; i++) {
            float4 p = *reinterpret_cast<const float4*>(P + (ig*2 + i)*Dn);
            acc[i][0] = p.x; acc[i][1] = p.y; acc[i][2] = p.z; acc[i][3] = p.w;
        }
    }

    {
        const int base = (b*Tn + c*TC) * Dn;
        if (tid < 128) {
            const int t = tid >> 3, jj = (tid & 7)*4;
            *reinterpret_cast<float4*>(Kc + t*32 + jj) =
                *reinterpret_cast<const float4*>(g_K + base + t*Dn + jh*32 + jj);
        }
        {
            const int t = tid >> 4, jj = (tid & 15)*4;
            *reinterpret_cast<float4*>(Qc + t*Dn + jj) =
                *reinterpret_cast<const float4*>(g_Q + base + t*Dn + jj);
            *reinterpret_cast<float4*>(Vc + t*Dn + jj) =
                *reinterpret_cast<const float4*>(g_V + base + t*Dn + jj);
        }
    }
    __syncthreads();

    float* yout = out;
    float* sout = out + (size_t)ROWS * Dn;
    const int rbase0 = b*Tn + c*TC;

#pragma unroll 1
    for (int tg = 0; tg < TC/8; tg++) {
#pragma unroll
        for (int tt = 0; tt < 8; tt++) {
            const int t = tg*8 + tt;
            float4 k4 = *reinterpret_cast<const float4*>(Kc + t*32 + jg*4);
            float2 q2 = *reinterpret_cast<const float2*>(Qc + t*Dn + ig*2);
            float2 v2 = *reinterpret_cast<const float2*>(Vc + t*Dn + ig*2);
            const float kk[4] = {k4.x, k4.y, k4.z, k4.w};
            float yp[4] = {0.f, 0.f, 0.f, 0.f};
            float* srow = sout + (size_t)(rbase0 + t)*(Dn*Dn) + jh*32 + jg*4;

#pragma unroll
            for (int e = 0; e < 4; e++) { acc[0][e] += v2.x*kk[e]; yp[e] += acc[0][e]*q2.x; }
            __stcs(reinterpret_cast<float4*>(srow + (ig*2)*Dn),
                   make_float4(acc[0][0], acc[0][1], acc[0][2], acc[0][3]));
#pragma unroll
            for (int e = 0; e < 4; e++) { acc[1][e] += v2.y*kk[e]; yp[e] += acc[1][e]*q2.y; }
            __stcs(reinterpret_cast<float4*>(srow + (ig*2 + 1)*Dn),
                   make_float4(acc[1][0], acc[1][1], acc[1][2], acc[1][3]));

#pragma unroll
            for (int e = 0; e < 4; e++) {
                yp[e] += __shfl_xor_sync(0xffffffffu, yp[e], 8);
                yp[e] += __shfl_xor_sync(0xffffffffu, yp[e], 16);
            }
            if (l < 8) ypbuf[(tt*8 + w)*8 + l] = make_float4(yp[0], yp[1], yp[2], yp[3]);
        }
        __syncthreads();
        if (tid < 64) {
            const int tt = tid >> 3, jp = tid & 7;
            float4 s = make_float4(0.f, 0.f, 0.f, 0.f);
#pragma unroll
            for (int w8 = 0; w8 < 8; w8++) {
                float4 v = ypbuf[(tt*8 + w8)*8 + jp];
                s.x += v.x; s.y += v.y; s.z += v.z; s.w += v.w;
            }
            __stcs(reinterpret_cast<float4*>(
                yout + (size_t)(rbase0 + tg*8 + tt)*Dn + jh*32 + jp*4), s);
        }
        __syncthreads();
    }
}

// ---------------------------------------------------------------------------
extern "C" void kernel_launch(void* const* d_in, const int* in_sizes, int n_in,
                              void* d_out, int out_size)
{
    const float* x     = (const float*)d_in[0];
    const float* state = (const float*)d_in[1];
    const float* Wk    = (const float*)d_in[2];
    const float* Wq    = (const float*)d_in[3];
    const float* Wv    = (const float*)d_in[4];
    const float* gamma = (const float*)d_in[5];
    const float* beta  = (const float*)d_in[6];
    float* out = (float*)d_out;

    static cudaStream_t s1 = nullptr;
    static cudaEvent_t evA = nullptr, evB = nullptr;
    if (s1 == nullptr) {
        cudaStreamCreateWithFlags(&s1, cudaStreamNonBlocking);
        cudaEventCreateWithFlags(&evA, cudaEventDisableTiming);
        cudaEventCreateWithFlags(&evB, cudaEventDisableTiming);
        cudaFuncSetAttribute(gemm_kv_kernel, cudaFuncAttributeMaxDynamicSharedMemorySize, FSM_TOT);
        cudaFuncSetAttribute(gemm_q_kernel,  cudaFuncAttributeMaxDynamicSharedMemorySize, SM_TOT);
        cudaFuncSetAttribute(scan_kernel,    cudaFuncAttributeMaxDynamicSharedMemorySize, SC_TOTF*4);
    }

    prep_kernel<<<256 + NTOT, 256>>>(x, Wk, Wq, Wv, gamma, beta);
    cudaEventRecord(evA, 0);

    cudaStreamWaitEvent(s1, evA, 0);
    gemm_q_kernel<<<ROWS/MBLK, 256, SM_TOT, s1>>>();
    cudaEventRecord(evB, s1);

    gemm_kv_kernel<<<ROWS/MBLK, 256, FSM_TOT>>>();
    prefix_kernel<<<dim3(128, Bn), 256>>>(state);

    cudaStreamWaitEvent(0, evB, 0);
    scan_kernel<<<dim3(NCH, Bn, 2), 256, SC_TOTF*4>>>(out);
}

// round 16
// speedup vs baseline: 1.0758x; 1.0446x over previous
#include <cuda_runtime.h>
#include <cuda_bf16.h>

// Problem constants
#define Bn 8
#define Tn 1024
#define Fn 512
#define Dn 64
#define ROWS (Bn*Tn)       // 8192
#define TC 16              // scan chunk length
#define NCH 64             // scan chunks (Tn/TC)
#define NGRP 16            // 4-chunk groups per batch

// GEMM tiling
#define MBLK 64            // rows per block
#define NTOT 192           // total W rows (K|Q|V)
#define NKC2 8             // K chunks of 64
#define LDB2 144           // smem row stride bytes (64 bf16 = 128B + 16 pad)
#define OUTS 68            // Q epilogue fp32 tile stride
#define OUTS2 132          // KV epilogue fp32 tile stride (128 + 4)

// Q-GEMM smem (N=64): 2 stages of {A_hi,A_lo,B_hi,B_lo} 64 rows x 144B
#define SA_HI 0
#define SA_LO 9216
#define SB_HI 18432
#define SB_LO 27648
#define STGB  36864
#define SM_TOT (2*STGB)    // 73728

// KV-GEMM smem (N=128): 2 stages of {A_hi,A_lo (64r), B_hi,B_lo (128r)}
#define FA_HI 0
#define FA_LO 9216
#define FB_HI 18432
#define FB_LO 36864
#define FSTGB 55296
#define FSM_TOT (2*FSTGB)  // 110592

// Scan smem layout (floats)
#define SC_KC   0                      // [16][32]
#define SC_QC   (SC_KC + TC*32)        // [16][64]
#define SC_VC   (SC_QC + TC*Dn)        // [16][64]
#define SC_YP   (SC_VC + TC*Dn)        // float4[8][8][8] = 2048 floats
#define SC_TOTF (SC_YP + 8*8*8*4)      // 4608 floats = 18432 B

// Scratch
__device__ float g_K[ROWS*Dn];
__device__ float g_Q[ROWS*Dn];
__device__ float g_V[ROWS*Dn];
__device__ float g_S[Bn*NCH*Dn*Dn];        // 8MB CUMULATIVE chunk sums (within 4-chunk group)
__device__ float g_GP[Bn*NGRP*Dn*Dn];      // 2MB group-prefix states (incl. initial state)
__device__ unsigned short g_Whi[NTOT*Fn];
__device__ unsigned short g_Wlo[NTOT*Fn];
__device__ unsigned short g_Xhi[ROWS*Fn];
__device__ unsigned short g_Xlo[ROWS*Fn];

__device__ __forceinline__ unsigned smem_u32(const void* p){
    unsigned a;
    asm("{ .reg .u64 t; cvta.to.shared.u64 t, %1; cvt.u32.u64 %0, t; }" : "=r"(a) : "l"(p));
    return a;
}
__device__ __forceinline__ void cp16(unsigned dst, const void* src){
    asm volatile("cp.async.cg.shared.global [%0], [%1], 16;" :: "r"(dst), "l"(src));
}
#define CP_COMMIT() asm volatile("cp.async.commit_group;" ::: "memory")
#define CP_WAIT(n)  asm volatile("cp.async.wait_group %0;" :: "n"(n) : "memory")

#define LDSM4(r, addr) \
    asm volatile("ldmatrix.sync.aligned.m8n8.x4.shared.b16 {%0,%1,%2,%3}, [%4];" \
        : "=r"((r)[0]), "=r"((r)[1]), "=r"((r)[2]), "=r"((r)[3]) : "r"(addr))

#define MMA_BF16(d, a, b0, b1) \
    asm volatile("mma.sync.aligned.m16n8k16.row.col.f32.bf16.bf16.f32 " \
        "{%0,%1,%2,%3}, {%4,%5,%6,%7}, {%8,%9}, {%0,%1,%2,%3};" \
        : "+f"((d)[0]), "+f"((d)[1]), "+f"((d)[2]), "+f"((d)[3]) \
        : "r"((a)[0]), "r"((a)[1]), "r"((a)[2]), "r"((a)[3]), "r"(b0), "r"(b1))

__device__ __forceinline__ unsigned pack_bf2(float v0, float v1, unsigned short* lo0, unsigned short* lo1){
    __nv_bfloat16 h0 = __float2bfloat16(v0);
    __nv_bfloat16 h1 = __float2bfloat16(v1);
    *lo0 = __bfloat16_as_ushort(__float2bfloat16(v0 - __bfloat162float(h0)));
    *lo1 = __bfloat16_as_ushort(__float2bfloat16(v1 - __bfloat162float(h1)));
    return (unsigned)__bfloat16_as_ushort(h0) | ((unsigned)__bfloat16_as_ushort(h1) << 16);
}

// ---------------------------------------------------------------------------
// Fused prep: blocks [0,256) = LN+split x ; blocks [256,448) = W transpose+split
// ---------------------------------------------------------------------------
__global__ void __launch_bounds__(256) prep_kernel(
    const float* __restrict__ x,
    const float* __restrict__ Wk, const float* __restrict__ Wq,
    const float* __restrict__ Wv,
    const float* __restrict__ gamma, const float* __restrict__ beta)
{
    if (blockIdx.x >= 256) {
        const int n = blockIdx.x - 256;
        const int m = n >> 6, j = n & 63;
        const float* W = (m == 0) ? Wk : ((m == 1) ? Wq : Wv);
        const int k0 = threadIdx.x * 2;
        float v0 = __ldg(W + (size_t)k0*Dn + j);
        float v1 = __ldg(W + (size_t)(k0+1)*Dn + j);
        unsigned short l0, l1;
        unsigned hi = pack_bf2(v0, v1, &l0, &l1);
        unsigned lo = (unsigned)l0 | ((unsigned)l1 << 16);
        reinterpret_cast<unsigned*>(g_Whi)[n*(Fn/2) + threadIdx.x] = hi;
        reinterpret_cast<unsigned*>(g_Wlo)[n*(Fn/2) + threadIdx.x] = lo;
        return;
    }
    const int w = threadIdx.x >> 5, l = threadIdx.x & 31;
#pragma unroll 1
    for (int rr = 0; rr < 4; rr++) {
        const int row = blockIdx.x*32 + w*4 + rr;
        const float4* xr = reinterpret_cast<const float4*>(x + (size_t)row * Fn);
        float4 v[4];
        float s = 0.f, ss = 0.f;
#pragma unroll
        for (int q = 0; q < 4; q++) {
            v[q] = xr[q*32 + l];
            s  += v[q].x + v[q].y + v[q].z + v[q].w;
            ss += v[q].x*v[q].x + v[q].y*v[q].y + v[q].z*v[q].z + v[q].w*v[q].w;
        }
#pragma unroll
        for (int o = 16; o; o >>= 1) {
            s  += __shfl_xor_sync(0xffffffffu, s,  o);
            ss += __shfl_xor_sync(0xffffffffu, ss, o);
        }
        const float mu   = s * (1.f/512.f);
        const float var  = ss * (1.f/512.f) - mu*mu;
        const float rstd = rsqrtf(var + 1e-5f);
#pragma unroll
        for (int q = 0; q < 4; q++) {
            const int c4 = q*32 + l;
            float4 g4 = __ldg(reinterpret_cast<const float4*>(gamma) + c4);
            float4 b4 = __ldg(reinterpret_cast<const float4*>(beta)  + c4);
            float vv[4] = {v[q].x, v[q].y, v[q].z, v[q].w};
            float gg[4] = {g4.x, g4.y, g4.z, g4.w};
            float bb[4] = {b4.x, b4.y, b4.z, b4.w};
#pragma unroll
            for (int e = 0; e < 4; e++) vv[e] = (vv[e] - mu)*rstd*gg[e] + bb[e];
            unsigned short s0, s1, s2, s3;
            unsigned h0 = pack_bf2(vv[0], vv[1], &s0, &s1);
            unsigned h1 = pack_bf2(vv[2], vv[3], &s2, &s3);
            unsigned lo0 = (unsigned)s0 | ((unsigned)s1 << 16);
            unsigned lo1 = (unsigned)s2 | ((unsigned)s3 << 16);
            *reinterpret_cast<uint2*>(g_Xhi + (size_t)row*Fn + c4*4) = make_uint2(h0, h1);
            *reinterpret_cast<uint2*>(g_Xlo + (size_t)row*Fn + c4*4) = make_uint2(lo0, lo1);
        }
    }
}

// ---------------------------------------------------------------------------
// Fused KV-GEMM + cumulative chunk-sums. grid 128, 256 threads.
// ---------------------------------------------------------------------------
__global__ void __launch_bounds__(256) gemm_kv_kernel()
{
    extern __shared__ char smem[];
    const int tid = threadIdx.x, w = tid >> 5, l = tid & 31;
    const int mb = blockIdx.x;
    const int row0 = mb * MBLK;
    const unsigned sbase = smem_u32(smem);
    const int wm = w & 1, wn = w >> 1;

    const int sr = tid >> 2, seg = tid & 3;
    const char* srcAh = (const char*)(g_Xhi + (size_t)(row0 + sr)*Fn) + seg*32;
    const char* srcAl = (const char*)(g_Xlo + (size_t)(row0 + sr)*Fn) + seg*32;
    const char* srcB0h = (const char*)(g_Whi + (size_t)sr*Fn) + seg*32;
    const char* srcB0l = (const char*)(g_Wlo + (size_t)sr*Fn) + seg*32;
    const char* srcB1h = (const char*)(g_Whi + (size_t)(128 + sr)*Fn) + seg*32;
    const char* srcB1l = (const char*)(g_Wlo + (size_t)(128 + sr)*Fn) + seg*32;
    const unsigned dA  = sbase + (unsigned)sr*LDB2 + seg*32;
    const unsigned dB0 = sbase + (unsigned)sr*LDB2 + seg*32;
    const unsigned dB1 = sbase + (unsigned)(64 + sr)*LDB2 + seg*32;

    unsigned a_off[2], b_off[2];
#pragma unroll
    for (int mt = 0; mt < 2; mt++)
        a_off[mt] = sbase + FA_HI + (unsigned)(wm*32 + mt*16 + (l & 15))*LDB2 + ((l >> 4) << 4);
#pragma unroll
    for (int bb = 0; bb < 2; bb++)
        b_off[bb] = sbase + FB_HI
            + (unsigned)(wn*32 + bb*16 + ((l >> 4) << 3) + (l & 7))*LDB2 + (((l >> 3) & 1) << 4);

    float acc[2][4][4];
#pragma unroll
    for (int mt = 0; mt < 2; mt++)
#pragma unroll
        for (int nt = 0; nt < 4; nt++)
#pragma unroll
            for (int e = 0; e < 4; e++) acc[mt][nt][e] = 0.f;

    {
        cp16(dA + FA_HI, srcAh);   cp16(dA + FA_HI + 16, srcAh + 16);
        cp16(dA + FA_LO, srcAl);   cp16(dA + FA_LO + 16, srcAl + 16);
        cp16(dB0 + FB_HI, srcB0h); cp16(dB0 + FB_HI + 16, srcB0h + 16);
        cp16(dB0 + FB_LO, srcB0l); cp16(dB0 + FB_LO + 16, srcB0l + 16);
        cp16(dB1 + FB_HI, srcB1h); cp16(dB1 + FB_HI + 16, srcB1h + 16);
        cp16(dB1 + FB_LO, srcB1l); cp16(dB1 + FB_LO + 16, srcB1l + 16);
        CP_COMMIT();
    }

#pragma unroll 1
    for (int c = 0; c < NKC2; c++) {
        if (c < NKC2 - 1) {
            const unsigned st = ((c + 1) & 1)*FSTGB;
            const int o = (c + 1)*128;
            cp16(dA + st + FA_HI, srcAh + o);   cp16(dA + st + FA_HI + 16, srcAh + o + 16);
            cp16(dA + st + FA_LO, srcAl + o);   cp16(dA + st + FA_LO + 16, srcAl + o + 16);
            cp16(dB0 + st + FB_HI, srcB0h + o); cp16(dB0 + st + FB_HI + 16, srcB0h + o + 16);
            cp16(dB0 + st + FB_LO, srcB0l + o); cp16(dB0 + st + FB_LO + 16, srcB0l + o + 16);
            cp16(dB1 + st + FB_HI, srcB1h + o); cp16(dB1 + st + FB_HI + 16, srcB1h + o + 16);
            cp16(dB1 + st + FB_LO, srcB1l + o); cp16(dB1 + st + FB_LO + 16, srcB1l + o + 16);
            CP_COMMIT();
            CP_WAIT(1);
        } else {
            CP_WAIT(0);
        }
        __syncthreads();

        const unsigned so = (unsigned)(c & 1)*FSTGB;
#pragma unroll
        for (int ks = 0; ks < 4; ks++) {
            const unsigned koff = so + ks*32;
            unsigned ahi[2][4], alo[2][4], bhi[2][4], blo[2][4];
#pragma unroll
            for (int mt = 0; mt < 2; mt++) {
                LDSM4(ahi[mt], a_off[mt] + koff);
                LDSM4(alo[mt], a_off[mt] + koff + (FA_LO - FA_HI));
            }
#pragma unroll
            for (int bb = 0; bb < 2; bb++) {
                LDSM4(bhi[bb], b_off[bb] + koff);
                LDSM4(blo[bb], b_off[bb] + koff + (FB_LO - FB_HI));
            }
#pragma unroll
            for (int mt = 0; mt < 2; mt++)
#pragma unroll
                for (int nt = 0; nt < 4; nt++) {
                    const int p = nt >> 1, h = (nt & 1)*2;
                    MMA_BF16(acc[mt][nt], ahi[mt], bhi[p][h], bhi[p][h+1]);
                    MMA_BF16(acc[mt][nt], ahi[mt], blo[p][h], blo[p][h+1]);
                    MMA_BF16(acc[mt][nt], alo[mt], bhi[p][h], bhi[p][h+1]);
                }
        }
        __syncthreads();
    }

    float* outt = reinterpret_cast<float*>(smem);
#pragma unroll
    for (int mt = 0; mt < 2; mt++)
#pragma unroll
        for (int nt = 0; nt < 4; nt++) {
            const int r   = wm*32 + mt*16 + (l >> 2);
            const int col = wn*32 + nt*8 + (l & 3)*2;
            *reinterpret_cast<float2*>(&outt[r*OUTS2 + col])     = make_float2(acc[mt][nt][0], acc[mt][nt][1]);
            *reinterpret_cast<float2*>(&outt[(r+8)*OUTS2 + col]) = make_float2(acc[mt][nt][2], acc[mt][nt][3]);
        }
    __syncthreads();

#pragma unroll 1
    for (int r8 = 0; r8 < 8; r8++) {
        const int r = w*8 + r8;
        const int grow = row0 + r;
        float k0 = fmaxf(outt[r*OUTS2 + l], 0.f);
        float k1 = fmaxf(outt[r*OUTS2 + 32 + l], 0.f);
        float s = k0 + k1;
#pragma unroll
        for (int o = 16; o; o >>= 1) s += __shfl_xor_sync(0xffffffffu, s, o);
        const float rs = 1.f / (1e-5f + s);
        k0 *= rs; k1 *= rs;
        outt[r*OUTS2 + l]      = k0;
        outt[r*OUTS2 + 32 + l] = k1;
        g_K[(size_t)grow*Dn + l]      = k0;
        g_K[(size_t)grow*Dn + 32 + l] = k1;
        g_V[(size_t)grow*Dn + l]      = outt[r*OUTS2 + 64 + l];
        g_V[(size_t)grow*Dn + 32 + l] = outt[r*OUTS2 + 96 + l];
    }
    __syncthreads();

    // CUMULATIVE chunk sums within this block's 4-chunk group
    const int jg = tid & 15, ig = tid >> 4;
    float a4[4][4] = {};
#pragma unroll 1
    for (int ch = 0; ch < 4; ch++) {
#pragma unroll
        for (int t = 0; t < TC; t++) {
            const int row = ch*16 + t;
            float4 k4 = *reinterpret_cast<const float4*>(&outt[row*OUTS2 + jg*4]);
            float4 v4 = *reinterpret_cast<const float4*>(&outt[row*OUTS2 + 64 + ig*4]);
            float kk[4] = {k4.x, k4.y, k4.z, k4.w};
            float vv[4] = {v4.x, v4.y, v4.z, v4.w};
#pragma unroll
            for (int i = 0; i < 4; i++)
#pragma unroll
                for (int j = 0; j < 4; j++) a4[i][j] += vv[i]*kk[j];
        }
        float* S = g_S + (size_t)(mb*4 + ch)*(Dn*Dn);
#pragma unroll
        for (int i = 0; i < 4; i++)
            *reinterpret_cast<float4*>(S + (ig*4 + i)*Dn + jg*4) =
                make_float4(a4[i][0], a4[i][1], a4[i][2], a4[i][3]);
    }
}

// ---------------------------------------------------------------------------
// Q-GEMM: grid 128, 256 threads (8 warps: 2M x 4N(16)), cp.async 2-stage.
// ---------------------------------------------------------------------------
__global__ void __launch_bounds__(256) gemm_q_kernel()
{
    extern __shared__ char smem[];
    const int tid = threadIdx.x, w = tid >> 5, l = tid & 31;
    const int mb = blockIdx.x;
    const int row0 = mb * MBLK;
    const unsigned sbase = smem_u32(smem);
    const int wm = w & 1, wn = w >> 1;

    const int sr = tid >> 2, seg = tid & 3;
    const char* srcAh = (const char*)(g_Xhi + (size_t)(row0 + sr)*Fn) + seg*32;
    const char* srcAl = (const char*)(g_Xlo + (size_t)(row0 + sr)*Fn) + seg*32;
    const char* srcBh = (const char*)(g_Whi + (size_t)(64 + sr)*Fn) + seg*32;
    const char* srcBl = (const char*)(g_Wlo + (size_t)(64 + sr)*Fn) + seg*32;
    const unsigned dbase = sbase + (unsigned)sr*LDB2 + seg*32;

    unsigned a_off[2];
#pragma unroll
    for (int mt = 0; mt < 2; mt++)
        a_off[mt] = sbase + SA_HI + (unsigned)(wm*32 + mt*16 + (l & 15))*LDB2 + ((l >> 4) << 4);
    const unsigned b_off = sbase + SB_HI
        + (unsigned)(wn*16 + ((l >> 4) << 3) + (l & 7))*LDB2 + (((l >> 3) & 1) << 4);

    float acc[2][2][4];
#pragma unroll
    for (int mt = 0; mt < 2; mt++)
#pragma unroll
        for (int nt = 0; nt < 2; nt++)
#pragma unroll
            for (int e = 0; e < 4; e++) acc[mt][nt][e] = 0.f;

    {
        const unsigned d = dbase;
        cp16(d + SA_HI, srcAh);  cp16(d + SA_HI + 16, srcAh + 16);
        cp16(d + SA_LO, srcAl);  cp16(d + SA_LO + 16, srcAl + 16);
        cp16(d + SB_HI, srcBh);  cp16(d + SB_HI + 16, srcBh + 16);
        cp16(d + SB_LO, srcBl);  cp16(d + SB_LO + 16, srcBl + 16);
        CP_COMMIT();
    }

#pragma unroll 1
    for (int c = 0; c < NKC2; c++) {
        if (c < NKC2 - 1) {
            const unsigned d = dbase + ((c + 1) & 1)*STGB;
            const int o = (c + 1)*128;
            cp16(d + SA_HI, srcAh + o);  cp16(d + SA_HI + 16, srcAh + o + 16);
            cp16(d + SA_LO, srcAl + o);  cp16(d + SA_LO + 16, srcAl + o + 16);
            cp16(d + SB_HI, srcBh + o);  cp16(d + SB_HI + 16, srcBh + o + 16);
            cp16(d + SB_LO, srcBl + o);  cp16(d + SB_LO + 16, srcBl + o + 16);
            CP_COMMIT();
            CP_WAIT(1);
        } else {
            CP_WAIT(0);
        }
        __syncthreads();

        const unsigned so = (unsigned)(c & 1)*STGB;
#pragma unroll
        for (int ks = 0; ks < 4; ks++) {
            const unsigned koff = so + ks*32;
            unsigned ahi[2][4], alo[2][4], bhi[4], blo[4];
#pragma unroll
            for (int mt = 0; mt < 2; mt++) {
                LDSM4(ahi[mt], a_off[mt] + koff);
                LDSM4(alo[mt], a_off[mt] + koff + (SA_LO - SA_HI));
            }
            LDSM4(bhi, b_off + koff);
            LDSM4(blo, b_off + koff + (SB_LO - SB_HI));
#pragma unroll
            for (int mt = 0; mt < 2; mt++)
#pragma unroll
                for (int nt = 0; nt < 2; nt++) {
                    const int h = nt*2;
                    MMA_BF16(acc[mt][nt], ahi[mt], bhi[h], bhi[h+1]);
                    MMA_BF16(acc[mt][nt], ahi[mt], blo[h], blo[h+1]);
                    MMA_BF16(acc[mt][nt], alo[mt], bhi[h], bhi[h+1]);
                }
        }
        __syncthreads();
    }

    float* outt = reinterpret_cast<float*>(smem);
#pragma unroll
    for (int mt = 0; mt < 2; mt++)
#pragma unroll
        for (int nt = 0; nt < 2; nt++) {
            const int r   = wm*32 + mt*16 + (l >> 2);
            const int col = wn*16 + nt*8 + (l & 3)*2;
            *reinterpret_cast<float2*>(&outt[r*OUTS + col])     = make_float2(acc[mt][nt][0], acc[mt][nt][1]);
            *reinterpret_cast<float2*>(&outt[(r+8)*OUTS + col]) = make_float2(acc[mt][nt][2], acc[mt][nt][3]);
        }
    __syncthreads();

#pragma unroll 1
    for (int r8 = 0; r8 < 8; r8++) {
        const int r = w*8 + r8;
        const int grow = row0 + r;
        float v0 = fmaxf(outt[r*OUTS + l], 0.f);
        float v1 = fmaxf(outt[r*OUTS + 32 + l], 0.f);
        float s = v0 + v1;
#pragma unroll
        for (int o = 16; o; o >>= 1) s += __shfl_xor_sync(0xffffffffu, s, o);
        const float rs = 1.f / (1e-5f + s);
        g_Q[(size_t)grow*Dn + l]      = v0 * rs;
        g_Q[(size_t)grow*Dn + 32 + l] = v1 * rs;
    }
}

// ---------------------------------------------------------------------------
// Group prefix: GP[b][g] = state + sum of group totals (g' < g).
// Group total = cumulative tile g_S[b*NCH + g*4 + 3].
// grid (64, Bn) = 512 blocks, 256 threads; block = 16 float4 elements x 16 groups.
// Width-16 shfl scan, 2 elements per warp (lane halves).
// ---------------------------------------------------------------------------
__global__ void __launch_bounds__(256) prefix_kernel(const float* __restrict__ state)
{
    __shared__ float sp[4][NGRP][17];
    const int b = blockIdx.y, eb = blockIdx.x;
    const int tid = threadIdx.x, w = tid >> 5, l = tid & 31;

    // Phase 1: load group-total tiles (coalesced 256B segments)
    {
        const int gp = tid >> 4, el = tid & 15;
        float4 v = *reinterpret_cast<const float4*>(
            g_S + (size_t)(b*NCH + gp*4 + 3)*(Dn*Dn) + (eb*16 + el)*4);
        sp[0][gp][el] = v.x; sp[1][gp][el] = v.y;
        sp[2][gp][el] = v.z; sp[3][gp][el] = v.w;
    }
    __syncthreads();

    // Phase 2: warp w handles elements w*2 + (lane>=16); lg = lane & 15 = group
    {
        const int el = w*2 + (l >> 4);
        const int lg = l & 15;
        float4 st = __ldg(reinterpret_cast<const float4*>(
            state + (size_t)b*(Dn*Dn) + (eb*16 + el)*4));
        const float stv[4] = {st.x, st.y, st.z, st.w};
#pragma unroll
        for (int p = 0; p < 4; p++) {
            float v = sp[p][lg][el];
            float inc = v;
#pragma unroll
            for (int o = 1; o < 16; o <<= 1) {
                float a = __shfl_up_sync(0xffffffffu, inc, o, 16);
                if (lg >= o) inc += a;
            }
            sp[p][lg][el] = stv[p] + (inc - v);   // exclusive + state
        }
    }
    __syncthreads();

    // Phase 3: store GP
    {
        const int gp = tid >> 4, el = tid & 15;
        float4 v = make_float4(sp[0][gp][el], sp[1][gp][el],
                               sp[2][gp][el], sp[3][gp][el]);
        *reinterpret_cast<float4*>(
            g_GP + (size_t)(b*NGRP + gp)*(Dn*Dn) + (eb*16 + el)*4) = v;
    }
}

// ---------------------------------------------------------------------------
// Scan: grid (NCH, Bn, 2 j-halves) = 1024 blocks, 256 threads, TC=16.
// Offset = GP[b][c/4]  (+ cumulative C[b][c-1] if c%4 != 0).
// ---------------------------------------------------------------------------
__global__ void __launch_bounds__(256) scan_kernel(float* __restrict__ out)
{
    extern __shared__ float sm[];
    float*  Kc = sm + SC_KC;
    float*  Qc = sm + SC_QC;
    float*  Vc = sm + SC_VC;
    float4* ypbuf = reinterpret_cast<float4*>(sm + SC_YP);

    const int c = blockIdx.x, b = blockIdx.y, jh = blockIdx.z;
    const int tid = threadIdx.x, w = tid >> 5, l = tid & 31;
    const int ig = tid >> 3, jg = tid & 7;

    float acc[2][4];
    {
        const float* GP = g_GP + (size_t)(b*NGRP + (c >> 2))*(Dn*Dn) + jh*32 + jg*4;
#pragma unroll
        for (int i = 0; i < 2; i++) {
            float4 p = *reinterpret_cast<const float4*>(GP + (ig*2 + i)*Dn);
            acc[i][0] = p.x; acc[i][1] = p.y; acc[i][2] = p.z; acc[i][3] = p.w;
        }
        if (c & 3) {
            const float* Cp = g_S + (size_t)(b*NCH + c - 1)*(Dn*Dn) + jh*32 + jg*4;
#pragma unroll
            for (int i = 0; i < 2; i++) {
                float4 p = *reinterpret_cast<const float4*>(Cp + (ig*2 + i)*Dn);
                acc[i][0] += p.x; acc[i][1] += p.y; acc[i][2] += p.z; acc[i][3] += p.w;
            }
        }
    }

    {
        const int base = (b*Tn + c*TC) * Dn;
        if (tid < 128) {
            const int t = tid >> 3, jj = (tid & 7)*4;
            *reinterpret_cast<float4*>(Kc + t*32 + jj) =
                *reinterpret_cast<const float4*>(g_K + base + t*Dn + jh*32 + jj);
        }
        {
            const int t = tid >> 4, jj = (tid & 15)*4;
            *reinterpret_cast<float4*>(Qc + t*Dn + jj) =
                *reinterpret_cast<const float4*>(g_Q + base + t*Dn + jj);
            *reinterpret_cast<float4*>(Vc + t*Dn + jj) =
                *reinterpret_cast<const float4*>(g_V + base + t*Dn + jj);
        }
    }
    __syncthreads();

    float* yout = out;
    float* sout = out + (size_t)ROWS * Dn;
    const int rbase0 = b*Tn + c*TC;

#pragma unroll 1
    for (int tg = 0; tg < TC/8; tg++) {
#pragma unroll
        for (int tt = 0; tt < 8; tt++) {
            const int t = tg*8 + tt;
            float4 k4 = *reinterpret_cast<const float4*>(Kc + t*32 + jg*4);
            float2 q2 = *reinterpret_cast<const float2*>(Qc + t*Dn + ig*2);
            float2 v2 = *reinterpret_cast<const float2*>(Vc + t*Dn + ig*2);
            const float kk[4] = {k4.x, k4.y, k4.z, k4.w};
            float yp[4] = {0.f, 0.f, 0.f, 0.f};
            float* srow = sout + (size_t)(rbase0 + t)*(Dn*Dn) + jh*32 + jg*4;

#pragma unroll
            for (int e = 0; e < 4; e++) { acc[0][e] += v2.x*kk[e]; yp[e] += acc[0][e]*q2.x; }
            __stcs(reinterpret_cast<float4*>(srow + (ig*2)*Dn),
                   make_float4(acc[0][0], acc[0][1], acc[0][2], acc[0][3]));
#pragma unroll
            for (int e = 0; e < 4; e++) { acc[1][e] += v2.y*kk[e]; yp[e] += acc[1][e]*q2.y; }
            __stcs(reinterpret_cast<float4*>(srow + (ig*2 + 1)*Dn),
                   make_float4(acc[1][0], acc[1][1], acc[1][2], acc[1][3]));

#pragma unroll
            for (int e = 0; e < 4; e++) {
                yp[e] += __shfl_xor_sync(0xffffffffu, yp[e], 8);
                yp[e] += __shfl_xor_sync(0xffffffffu, yp[e], 16);
            }
            if (l < 8) ypbuf[(tt*8 + w)*8 + l] = make_float4(yp[0], yp[1], yp[2], yp[3]);
        }
        __syncthreads();
        if (tid < 64) {
            const int tt = tid >> 3, jp = tid & 7;
            float4 s = make_float4(0.f, 0.f, 0.f, 0.f);
#pragma unroll
            for (int w8 = 0; w8 < 8; w8++) {
                float4 v = ypbuf[(tt*8 + w8)*8 + jp];
                s.x += v.x; s.y += v.y; s.z += v.z; s.w += v.w;
            }
            __stcs(reinterpret_cast<float4*>(
                yout + (size_t)(rbase0 + tg*8 + tt)*Dn + jh*32 + jp*4), s);
        }
        __syncthreads();
    }
}

// ---------------------------------------------------------------------------
extern "C" void kernel_launch(void* const* d_in, const int* in_sizes, int n_in,
                              void* d_out, int out_size)
{
    const float* x     = (const float*)d_in[0];
    const float* state = (const float*)d_in[1];
    const float* Wk    = (const float*)d_in[2];
    const float* Wq    = (const float*)d_in[3];
    const float* Wv    = (const float*)d_in[4];
    const float* gamma = (const float*)d_in[5];
    const float* beta  = (const float*)d_in[6];
    float* out = (float*)d_out;

    static cudaStream_t s1 = nullptr;
    static cudaEvent_t evA = nullptr, evB = nullptr;
    if (s1 == nullptr) {
        cudaStreamCreateWithFlags(&s1, cudaStreamNonBlocking);
        cudaEventCreateWithFlags(&evA, cudaEventDisableTiming);
        cudaEventCreateWithFlags(&evB, cudaEventDisableTiming);
        cudaFuncSetAttribute(gemm_kv_kernel, cudaFuncAttributeMaxDynamicSharedMemorySize, FSM_TOT);
        cudaFuncSetAttribute(gemm_q_kernel,  cudaFuncAttributeMaxDynamicSharedMemorySize, SM_TOT);
        cudaFuncSetAttribute(scan_kernel,    cudaFuncAttributeMaxDynamicSharedMemorySize, SC_TOTF*4);
    }

    prep_kernel<<<256 + NTOT, 256>>>(x, Wk, Wq, Wv, gamma, beta);
    cudaEventRecord(evA, 0);

    cudaStreamWaitEvent(s1, evA, 0);
    gemm_q_kernel<<<ROWS/MBLK, 256, SM_TOT, s1>>>();
    cudaEventRecord(evB, s1);

    gemm_kv_kernel<<<ROWS/MBLK, 256, FSM_TOT>>>();
    prefix_kernel<<<dim3(64, Bn), 256>>>(state);

    cudaStreamWaitEvent(0, evB, 0);
    scan_kernel<<<dim3(NCH, Bn, 2), 256, SC_TOTF*4>>>(out);
}